// round 8
// baseline (speedup 1.0000x reference)
#include <cuda_runtime.h>
#include <cuda_bf16.h>
#include <math.h>
#include <stdint.h>

// ---------------- problem constants ----------------
#define S_  2048
#define D_  2048
#define H_  16
#define HD_ 128
#define E_  64
#define TOPK_ 2
#define HID_ 512
#define CAP_ 256
#define T_  (S_)
#define EPS_ 1e-6f
#define QKSCALE_ 0.08838834764831845f

// ---------------- scratch ----------------
__device__ float g_vf  [S_ * D_];
__device__ float g_h   [S_ * D_];
__device__ float g_hn  [S_ * D_];
__device__ int   g_top_e [T_ * TOPK_];
__device__ float g_top_s [T_ * TOPK_];
__device__ int   g_dest  [T_ * TOPK_];
__device__ int   g_count [E_];
__device__ int   g_slot_token[E_ * CAP_];
__device__ float g_slot_scale[E_ * CAP_];
__device__ float g_eout [E_ * CAP_ * D_];

// bf16 split activation planes
__device__ __nv_bfloat16 g_xnh[S_ * D_],  g_xnl[S_ * D_];
__device__ __nv_bfloat16 g_qh [S_ * D_],  g_ql [S_ * D_];
__device__ __nv_bfloat16 g_kh [S_ * D_],  g_kl [S_ * D_];
__device__ __nv_bfloat16 g_vth[D_ * S_],  g_vtl[D_ * S_];
__device__ __nv_bfloat16 g_ath[S_ * D_],  g_atl[S_ * D_];
__device__ __nv_bfloat16 g_bufh[E_ * CAP_ * D_], g_bufl[E_ * CAP_ * D_];
__device__ __nv_bfloat16 g_gateh[E_ * CAP_ * HID_], g_gatel[E_ * CAP_ * HID_];

// ---------------- helpers ----------------
__device__ __forceinline__ void bsplit(float v, __nv_bfloat16& h, __nv_bfloat16& l) {
    h = __float2bfloat16(v);
    l = __float2bfloat16(v - __bfloat162float(h));
}
__device__ __forceinline__ void split2(float x, float y, uint32_t& hi, uint32_t& lo) {
    __nv_bfloat16 hx = __float2bfloat16(x), hy = __float2bfloat16(y);
    __nv_bfloat16 lx = __float2bfloat16(x - __bfloat162float(hx));
    __nv_bfloat16 ly = __float2bfloat16(y - __bfloat162float(hy));
    __nv_bfloat162 hp = __halves2bfloat162(hx, hy);
    __nv_bfloat162 lp = __halves2bfloat162(lx, ly);
    hi = *(uint32_t*)&hp;
    lo = *(uint32_t*)&lp;
}

#define CP_ASYNC16(dst_sm, src_g) \
    asm volatile("cp.async.cg.shared.global [%0], [%1], 16;\n" :: "r"(dst_sm), "l"(src_g))

#define LDSM4(r, ptr) do { \
    uint32_t _a = (uint32_t)__cvta_generic_to_shared(ptr); \
    asm volatile("ldmatrix.sync.aligned.m8n8.x4.shared.b16 {%0,%1,%2,%3}, [%4];\n" \
                 : "=r"((r)[0]), "=r"((r)[1]), "=r"((r)[2]), "=r"((r)[3]) : "r"(_a)); \
} while (0)

#define MMA_BF16(d, a, b0, b1) \
    asm volatile("mma.sync.aligned.m16n8k16.row.col.f32.bf16.bf16.f32 " \
                 "{%0,%1,%2,%3}, {%4,%5,%6,%7}, {%8,%9}, {%0,%1,%2,%3};\n" \
                 : "+f"((d)[0]), "+f"((d)[1]), "+f"((d)[2]), "+f"((d)[3]) \
                 : "r"((a)[0]), "r"((a)[1]), "r"((a)[2]), "r"((a)[3]), "r"(b0), "r"(b1))

// ---------------- RMSNorm variants ----------------
__global__ void rmsnorm_kernel(const float* __restrict__ x,
                               const float* __restrict__ w,
                               float* __restrict__ out) {
    int s = blockIdx.x;
    const float* row = x + (long long)s * D_;
    float ss = 0.f;
    #pragma unroll
    for (int base = 0; base < D_; base += 1024) {
        float4 v = *(const float4*)(row + base + threadIdx.x * 4);
        ss += v.x * v.x + v.y * v.y + v.z * v.z + v.w * v.w;
    }
    __shared__ float red[256];
    red[threadIdx.x] = ss;
    __syncthreads();
    for (int off = 128; off > 0; off >>= 1) {
        if (threadIdx.x < off) red[threadIdx.x] += red[threadIdx.x + off];
        __syncthreads();
    }
    float scale = rsqrtf(red[0] / (float)D_ + EPS_);
    float* orow = out + (long long)s * D_;
    #pragma unroll
    for (int base = 0; base < D_; base += 1024) {
        int d = base + threadIdx.x * 4;
        float4 v = *(const float4*)(row + d);
        float4 ww = *(const float4*)(w + d);
        v.x *= scale * ww.x; v.y *= scale * ww.y;
        v.z *= scale * ww.z; v.w *= scale * ww.w;
        *(float4*)(orow + d) = v;
    }
}

__global__ void rmsnorm_split_kernel(const float* __restrict__ x,
                                     const float* __restrict__ w,
                                     __nv_bfloat16* __restrict__ oh,
                                     __nv_bfloat16* __restrict__ ol) {
    int s = blockIdx.x;
    const float* row = x + (long long)s * D_;
    float ss = 0.f;
    #pragma unroll
    for (int base = 0; base < D_; base += 1024) {
        float4 v = *(const float4*)(row + base + threadIdx.x * 4);
        ss += v.x * v.x + v.y * v.y + v.z * v.z + v.w * v.w;
    }
    __shared__ float red[256];
    red[threadIdx.x] = ss;
    __syncthreads();
    for (int off = 128; off > 0; off >>= 1) {
        if (threadIdx.x < off) red[threadIdx.x] += red[threadIdx.x + off];
        __syncthreads();
    }
    float scale = rsqrtf(red[0] / (float)D_ + EPS_);
    #pragma unroll
    for (int base = 0; base < D_; base += 1024) {
        int d = base + threadIdx.x * 4;
        float4 v = *(const float4*)(row + d);
        float4 ww = *(const float4*)(w + d);
        v.x *= scale * ww.x; v.y *= scale * ww.y;
        v.z *= scale * ww.z; v.w *= scale * ww.w;
        long long off = (long long)s * D_ + d;
        uint32_t h01, l01, h23, l23;
        split2(v.x, v.y, h01, l01);
        split2(v.z, v.w, h23, l23);
        *(uint2*)(oh + off) = make_uint2(h01, h23);
        *(uint2*)(ol + off) = make_uint2(l01, l23);
    }
}

// ---------------- split-free bf16 tensor-core GEMM (R7 config) --------------
template <int MODE, int SKIP, int BMODE, int MTILE>
__global__ __launch_bounds__(256, 2)
void gemm_os(const __nv_bfloat16* __restrict__ Ah, const __nv_bfloat16* __restrict__ Al,
             const float* __restrict__ B0, const float* __restrict__ B1,
             const float* __restrict__ B2,
             const float* __restrict__ ADD, float* __restrict__ C,
             int M, int N, int K,
             long long sA, long long sB, long long sC,
             const float* __restrict__ fcos, const float* __restrict__ fsin) {
    const int m0 = blockIdx.y * MTILE;
    if (SKIP) {
        if (m0 >= g_count[blockIdx.z]) return;
    }
    constexpr int AST = MTILE * 40;
    constexpr int MF  = MTILE / 32;
    extern __shared__ char smem_raw[];
    __nv_bfloat16* sAh = (__nv_bfloat16*)smem_raw;
    __nv_bfloat16* sAl = sAh + 2 * AST;
    float*         sBf = (float*)(sAl + 2 * AST);

    const __nv_bfloat16* Ahp = Ah + (long long)blockIdx.z * sA;
    const __nv_bfloat16* Alp = Al + (long long)blockIdx.z * sA;
    const long long bzsB = (long long)blockIdx.z * sB;
    C += (long long)blockIdx.z * sC;

    const int tid  = threadIdx.x;
    const int lane = tid & 31;
    const int warp = tid >> 5;
    const int wm = warp & 1;
    const int wn = warp >> 1;
    const int n0 = blockIdx.x * 128;

    float acc[MF][4][4];
    #pragma unroll
    for (int i = 0; i < MF; i++)
        #pragma unroll
        for (int j = 0; j < 4; j++)
            #pragma unroll
            for (int r = 0; r < 4; r++) acc[i][j][r] = 0.f;

    auto copyAB = [&](int stage, int k0) {
        __nv_bfloat16* sa = sAh + stage * AST;
        __nv_bfloat16* sl = sAl + stage * AST;
        #pragma unroll
        for (int i = 0; i < MTILE / 64; i++) {
            int ch  = tid + (i << 8);
            int row = ch >> 2;
            int c   = (ch & 3) << 3;
            const __nv_bfloat16* ap = Ahp + (size_t)(m0 + row) * K + k0 + c;
            const __nv_bfloat16* lp = Alp + (size_t)(m0 + row) * K + k0 + c;
            CP_ASYNC16((uint32_t)__cvta_generic_to_shared(sa + row * 40 + c), ap);
            CP_ASYNC16((uint32_t)__cvta_generic_to_shared(sl + row * 40 + c), lp);
        }
        float* sb = sBf + stage * 4608;
        #pragma unroll
        for (int i = 0; i < 4; i++) {
            int ch  = tid + (i << 8);
            int row = ch >> 3;
            int c   = (ch & 7) << 2;
            int n   = n0 + row;
            const float* src;
            if (BMODE == 0) {
                src = B0 + bzsB + (size_t)n * K;
            } else if (BMODE == 1) {
                int sel = n >> 11;
                const float* w = (sel == 0) ? B0 : ((sel == 1) ? B1 : B2);
                src = w + (size_t)(n & 2047) * K;
            } else {
                const float* w = (n & 1) ? B2 : B0;
                src = w + bzsB + (size_t)(n >> 1) * K;
            }
            CP_ASYNC16((uint32_t)__cvta_generic_to_shared(sb + row * 36 + c), src + k0 + c);
        }
        asm volatile("cp.async.commit_group;\n");
    };

    const int KT = K >> 5;
    copyAB(0, 0);
    if (KT > 1) copyAB(1, 32);

    for (int t = 0; t < KT; t++) {
        const int st = t & 1;
        if (t == KT - 1) {
            asm volatile("cp.async.wait_group 0;\n");
        } else {
            asm volatile("cp.async.wait_group 1;\n");
        }
        __syncthreads();
        const __nv_bfloat16* sa = sAh + st * AST;
        const __nv_bfloat16* sl = sAl + st * AST;
        const float* sb = sBf + st * 4608;

        #pragma unroll
        for (int ks = 0; ks < 32; ks += 16) {
            uint32_t bh[4][2], bl[4][2];
            const int bn = wn * 32 + (lane >> 2);
            const int bk = ks + ((lane & 3) << 1);
            #pragma unroll
            for (int g = 0; g < 4; g++) {
                const float* p = sb + (bn + g * 8) * 36 + bk;
                float2 x0 = *(const float2*)p;
                float2 x1 = *(const float2*)(p + 8);
                split2(x0.x, x0.y, bh[g][0], bl[g][0]);
                split2(x1.x, x1.y, bh[g][1], bl[g][1]);
            }
            const int ar = lane & 15;
            const int ac = ks + ((lane >> 4) << 3);
            #pragma unroll
            for (int mf = 0; mf < MF; mf++) {
                uint32_t a4[4];
                LDSM4(a4, sa + (wm * (MTILE / 2) + mf * 16 + ar) * 40 + ac);
                #pragma unroll
                for (int nf = 0; nf < 4; nf++)
                    MMA_BF16(acc[mf][nf], a4, bh[nf][0], bh[nf][1]);
                #pragma unroll
                for (int nf = 0; nf < 4; nf++)
                    MMA_BF16(acc[mf][nf], a4, bl[nf][0], bl[nf][1]);
                LDSM4(a4, sl + (wm * (MTILE / 2) + mf * 16 + ar) * 40 + ac);
                #pragma unroll
                for (int nf = 0; nf < 4; nf++)
                    MMA_BF16(acc[mf][nf], a4, bh[nf][0], bh[nf][1]);
            }
        }
        __syncthreads();
        if (t + 2 < KT) copyAB(st, (t + 2) << 5);
    }

    const int gq = lane >> 2, th = lane & 3;
    #pragma unroll
    for (int mf = 0; mf < MF; mf++) {
        #pragma unroll
        for (int nf = 0; nf < 4; nf++) {
            int row = m0 + wm * (MTILE / 2) + mf * 16 + gq;
            int col = n0 + wn * 32 + nf * 8 + th * 2;
            float2 v0 = make_float2(acc[mf][nf][0], acc[mf][nf][1]);
            float2 v1 = make_float2(acc[mf][nf][2], acc[mf][nf][3]);
            if (MODE == 0 || MODE == 1) {
                if (MODE == 1) {
                    float2 x0 = *(const float2*)(ADD + (size_t)row * N + col);
                    float2 x1 = *(const float2*)(ADD + (size_t)(row + 8) * N + col);
                    v0.x += x0.x; v0.y += x0.y;
                    v1.x += x1.x; v1.y += x1.y;
                }
                *(float2*)(C + (size_t)row * N + col) = v0;
                *(float2*)(C + (size_t)(row + 8) * N + col) = v1;
            } else if (MODE == 2) {
                int j = col >> 1;
                long long slot0 = (long long)blockIdx.z * CAP_ + row;
                float r0 = v0.x * (1.f / (1.f + __expf(-v0.x))) * v0.y;
                float r1 = v1.x * (1.f / (1.f + __expf(-v1.x))) * v1.y;
                __nv_bfloat16 hb, lb;
                bsplit(r0, hb, lb);
                g_gateh[slot0 * HID_ + j] = hb;
                g_gatel[slot0 * HID_ + j] = lb;
                bsplit(r1, hb, lb);
                g_gateh[(slot0 + 8) * HID_ + j] = hb;
                g_gatel[(slot0 + 8) * HID_ + j] = lb;
            } else {  // MODE 3
                if (col < 2 * D_) {
                    int lc = col & (D_ - 1);
                    int i  = (lc & 127) >> 1;
                    bool isq = col < D_;
                    float sc = isq ? QKSCALE_ : 1.f;
                    __nv_bfloat16* dh = isq ? g_qh : g_kh;
                    __nv_bfloat16* dl = isq ? g_ql : g_kl;
                    float c0 = fcos[row * 64 + i], s0 = fsin[row * 64 + i];
                    float y0 = (v0.x * c0 - v0.y * s0) * sc;
                    float y1 = (v0.x * s0 + v0.y * c0) * sc;
                    uint32_t hi, lo;
                    split2(y0, y1, hi, lo);
                    *(uint32_t*)(dh + (long long)row * D_ + lc) = hi;
                    *(uint32_t*)(dl + (long long)row * D_ + lc) = lo;
                    float c1 = fcos[(row + 8) * 64 + i], s1 = fsin[(row + 8) * 64 + i];
                    y0 = (v1.x * c1 - v1.y * s1) * sc;
                    y1 = (v1.x * s1 + v1.y * c1) * sc;
                    split2(y0, y1, hi, lo);
                    *(uint32_t*)(dh + (long long)(row + 8) * D_ + lc) = hi;
                    *(uint32_t*)(dl + (long long)(row + 8) * D_ + lc) = lo;
                } else {
                    int lc = col - 2 * D_;
                    *(float2*)(g_vf + (long long)row * D_ + lc) = v0;
                    *(float2*)(g_vf + (long long)(row + 8) * D_ + lc) = v1;
                }
            }
        }
    }
}

#define GEMM_SMEM_128 (2 * 2 * (128 * 40) * 2 + 2 * 4608 * 4)   // 77824 B
#define GEMM_SMEM_64  (2 * 2 * (64 * 40) * 2 + 2 * 4608 * 4)    // 57344 B

// ---------------- V transpose + split ----------------
__global__ void vtrans_kernel(__nv_bfloat16* __restrict__ vth,
                              __nv_bfloat16* __restrict__ vtl) {
    __shared__ float tile[32][33];
    int s0 = blockIdx.x * 32;
    int d0 = blockIdx.y * 32;
    int tx = threadIdx.x, ty = threadIdx.y;
    #pragma unroll
    for (int i = 0; i < 4; i++) {
        int r = ty + i * 8;
        tile[r][tx] = g_vf[(long long)(s0 + r) * D_ + d0 + tx];
    }
    __syncthreads();
    #pragma unroll
    for (int i = 0; i < 4; i++) {
        int dr = ty + i * 8;
        float v = tile[tx][dr];
        __nv_bfloat16 hv, lv;
        bsplit(v, hv, lv);
        long long off = (long long)(d0 + dr) * S_ + s0 + tx;
        vth[off] = hv;
        vtl[off] = lv;
    }
}

// ---------------- flash attention, bf16-split mma, double-buffered K/V -----
// 64 queries x 1 head per block, 128 threads; K/V tiles of 64 keys, 2 stages.
#define KBUF_ (2 * 64 * 136)     // elems per K stage (hi + lo)
#define VBUF_ (2 * 128 * 72)     // elems per V stage (hi + lo)
#define ATTN_SMEM ((2 * 64 * 136 + 2 * KBUF_ + 2 * VBUF_) * 2)   // 174080 B
__global__ __launch_bounds__(128)
void attn_mma_kernel(const __nv_bfloat16* __restrict__ qh, const __nv_bfloat16* __restrict__ ql,
                     const __nv_bfloat16* __restrict__ kh, const __nv_bfloat16* __restrict__ kl,
                     const __nv_bfloat16* __restrict__ vth, const __nv_bfloat16* __restrict__ vtl,
                     __nv_bfloat16* __restrict__ oh, __nv_bfloat16* __restrict__ ol) {
    extern __shared__ __nv_bfloat16 dsm[];
    __nv_bfloat16* sQh = dsm;                    // [64][136]
    __nv_bfloat16* sQl = sQh + 64 * 136;
    __nv_bfloat16* sK  = sQl + 64 * 136;         // [2][hi 64x136 | lo 64x136]
    __nv_bfloat16* sV  = sK + 2 * KBUF_;         // [2][hi 128x72 | lo 128x72]

    const int tid  = threadIdx.x;
    const int lane = tid & 31;
    const int warp = tid >> 5;
    const int h  = blockIdx.y;
    const int qb = gridDim.x - 1 - blockIdx.x;   // heavy blocks first
    const int q0 = qb * 64;
    const int row0 = warp * 16;

    auto loadKV = [&](int buf, int k0) {
        __nv_bfloat16* kdst = sK + buf * KBUF_;
        for (int c = tid; c < 1024; c += 128) {
            int r = c >> 4, j = (c & 15) << 3;
            long long g = (long long)(k0 + r) * D_ + h * HD_ + j;
            CP_ASYNC16((uint32_t)__cvta_generic_to_shared(kdst + r * 136 + j), kh + g);
            CP_ASYNC16((uint32_t)__cvta_generic_to_shared(kdst + 64 * 136 + r * 136 + j), kl + g);
        }
        __nv_bfloat16* vdst = sV + buf * VBUF_;
        for (int c = tid; c < 1024; c += 128) {
            int r = c >> 3, j = (c & 7) << 3;
            long long g = (long long)(h * HD_ + r) * S_ + k0 + j;
            CP_ASYNC16((uint32_t)__cvta_generic_to_shared(vdst + r * 72 + j), vth + g);
            CP_ASYNC16((uint32_t)__cvta_generic_to_shared(vdst + 128 * 72 + r * 72 + j), vtl + g);
        }
        asm volatile("cp.async.commit_group;\n");
    };

    // Q tile (persists) — group 0
    for (int c = tid; c < 1024; c += 128) {
        int r = c >> 4, j = (c & 15) << 3;
        long long g = (long long)(q0 + r) * D_ + h * HD_ + j;
        CP_ASYNC16((uint32_t)__cvta_generic_to_shared(sQh + r * 136 + j), qh + g);
        CP_ASYNC16((uint32_t)__cvta_generic_to_shared(sQl + r * 136 + j), ql + g);
    }
    asm volatile("cp.async.commit_group;\n");

    const int ntiles = qb + 1;
    loadKV(0, 0);                       // group 1
    if (ntiles > 1) loadKV(1, 64);      // group 2

    float m0 = -INFINITY, m1 = -INFINITY, l0 = 0.f, l1 = 0.f;
    float o[16][4];
    #pragma unroll
    for (int f = 0; f < 16; f++)
        #pragma unroll
        for (int r = 0; r < 4; r++) o[f][r] = 0.f;

    for (int kt = 0; kt < ntiles; kt++) {
        const int k0 = kt * 64;
        const int buf = kt & 1;
        if (kt == ntiles - 1) {
            asm volatile("cp.async.wait_group 0;\n");
        } else {
            asm volatile("cp.async.wait_group 1;\n");
        }
        __syncthreads();
        const __nv_bfloat16* cKh = sK + buf * KBUF_;
        const __nv_bfloat16* cKl = cKh + 64 * 136;
        const __nv_bfloat16* cVh = sV + buf * VBUF_;
        const __nv_bfloat16* cVl = cVh + 128 * 72;

        float sc[8][4];
        #pragma unroll
        for (int f = 0; f < 8; f++)
            #pragma unroll
            for (int r = 0; r < 4; r++) sc[f][r] = 0.f;

        #pragma unroll
        for (int ks = 0; ks < 8; ks++) {
            uint32_t ah[4], al[4];
            int ar = lane & 15;
            int ac = ks * 16 + ((lane >> 4) << 3);
            LDSM4(ah, sQh + (row0 + ar) * 136 + ac);
            LDSM4(al, sQl + (row0 + ar) * 136 + ac);
            int br = (lane & 7) + ((lane >> 4) << 3);
            int bc = ks * 16 + (((lane >> 3) & 1) << 3);
            #pragma unroll
            for (int g = 0; g < 4; g++) {
                uint32_t bh[4], bl[4];
                LDSM4(bh, cKh + (g * 16 + br) * 136 + bc);
                LDSM4(bl, cKl + (g * 16 + br) * 136 + bc);
                #pragma unroll
                for (int half = 0; half < 2; half++) {
                    int f = g * 2 + half;
                    MMA_BF16(sc[f], ah, bh[half * 2], bh[half * 2 + 1]);
                    MMA_BF16(sc[f], al, bh[half * 2], bh[half * 2 + 1]);
                    MMA_BF16(sc[f], ah, bl[half * 2], bl[half * 2 + 1]);
                }
            }
        }

        int qi0 = q0 + row0 + (lane >> 2);
        if (kt == ntiles - 1) {
            #pragma unroll
            for (int f = 0; f < 8; f++) {
                int ki = k0 + f * 8 + 2 * (lane & 3);
                if (ki > qi0)         sc[f][0] = -INFINITY;
                if (ki + 1 > qi0)     sc[f][1] = -INFINITY;
                if (ki > qi0 + 8)     sc[f][2] = -INFINITY;
                if (ki + 1 > qi0 + 8) sc[f][3] = -INFINITY;
            }
        }

        float mx0 = -INFINITY, mx1 = -INFINITY;
        #pragma unroll
        for (int f = 0; f < 8; f++) {
            mx0 = fmaxf(mx0, fmaxf(sc[f][0], sc[f][1]));
            mx1 = fmaxf(mx1, fmaxf(sc[f][2], sc[f][3]));
        }
        mx0 = fmaxf(mx0, __shfl_xor_sync(0xffffffff, mx0, 1));
        mx0 = fmaxf(mx0, __shfl_xor_sync(0xffffffff, mx0, 2));
        mx1 = fmaxf(mx1, __shfl_xor_sync(0xffffffff, mx1, 1));
        mx1 = fmaxf(mx1, __shfl_xor_sync(0xffffffff, mx1, 2));
        float nm0 = fmaxf(m0, mx0), nm1 = fmaxf(m1, mx1);
        float c0 = __expf(m0 - nm0), c1 = __expf(m1 - nm1);
        float rs0 = 0.f, rs1 = 0.f;
        #pragma unroll
        for (int f = 0; f < 8; f++) {
            sc[f][0] = __expf(sc[f][0] - nm0);
            sc[f][1] = __expf(sc[f][1] - nm0);
            sc[f][2] = __expf(sc[f][2] - nm1);
            sc[f][3] = __expf(sc[f][3] - nm1);
            rs0 += sc[f][0] + sc[f][1];
            rs1 += sc[f][2] + sc[f][3];
        }
        rs0 += __shfl_xor_sync(0xffffffff, rs0, 1);
        rs0 += __shfl_xor_sync(0xffffffff, rs0, 2);
        rs1 += __shfl_xor_sync(0xffffffff, rs1, 1);
        rs1 += __shfl_xor_sync(0xffffffff, rs1, 2);
        l0 = l0 * c0 + rs0;
        l1 = l1 * c1 + rs1;
        m0 = nm0; m1 = nm1;
        #pragma unroll
        for (int f = 0; f < 16; f++) {
            o[f][0] *= c0; o[f][1] *= c0;
            o[f][2] *= c1; o[f][3] *= c1;
        }

        #pragma unroll
        for (int ks = 0; ks < 4; ks++) {
            uint32_t ph[4], pl[4];
            split2(sc[2 * ks][0],     sc[2 * ks][1],     ph[0], pl[0]);
            split2(sc[2 * ks][2],     sc[2 * ks][3],     ph[1], pl[1]);
            split2(sc[2 * ks + 1][0], sc[2 * ks + 1][1], ph[2], pl[2]);
            split2(sc[2 * ks + 1][2], sc[2 * ks + 1][3], ph[3], pl[3]);
            int br = (lane & 7) + ((lane >> 4) << 3);
            int bc = ks * 16 + (((lane >> 3) & 1) << 3);
            #pragma unroll
            for (int g = 0; g < 8; g++) {
                uint32_t vbh[4], vbl[4];
                LDSM4(vbh, cVh + (g * 16 + br) * 72 + bc);
                LDSM4(vbl, cVl + (g * 16 + br) * 72 + bc);
                #pragma unroll
                for (int half = 0; half < 2; half++) {
                    int f = g * 2 + half;
                    MMA_BF16(o[f], ph, vbh[half * 2], vbh[half * 2 + 1]);
                    MMA_BF16(o[f], pl, vbh[half * 2], vbh[half * 2 + 1]);
                    MMA_BF16(o[f], ph, vbl[half * 2], vbl[half * 2 + 1]);
                }
            }
        }
        __syncthreads();
        if (kt + 2 < ntiles) loadKV(buf, (kt + 2) * 64);
    }

    float inv0 = 1.f / l0, inv1 = 1.f / l1;
    int qi0 = q0 + row0 + (lane >> 2);
    int qi1 = qi0 + 8;
    #pragma unroll
    for (int f = 0; f < 16; f++) {
        int gcol = h * HD_ + f * 8 + 2 * (lane & 3);
        uint32_t hi, lo;
        split2(o[f][0] * inv0, o[f][1] * inv0, hi, lo);
        *(uint32_t*)(oh + (long long)qi0 * D_ + gcol) = hi;
        *(uint32_t*)(ol + (long long)qi0 * D_ + gcol) = lo;
        split2(o[f][2] * inv1, o[f][3] * inv1, hi, lo);
        *(uint32_t*)(oh + (long long)qi1 * D_ + gcol) = hi;
        *(uint32_t*)(ol + (long long)qi1 * D_ + gcol) = lo;
    }
}

// ---------------- fused router: logits + softmax + top-2 ----------------
__global__ void router_topk_kernel(const float* __restrict__ hn,
                                   const float* __restrict__ rw) {
    __shared__ float sx[4][D_];
    __shared__ float slog[4][E_];
    int t0 = blockIdx.x * 4;
    int tid = threadIdx.x;
    for (int c = tid; c < 4 * (D_ / 4); c += 256) {
        int tok = c >> 9;
        int j = c & 511;
        ((float4*)sx[tok])[j] = ((const float4*)(hn + (long long)(t0 + tok) * D_))[j];
    }
    __syncthreads();
    int warp = tid >> 5, lane = tid & 31;
    for (int e8 = 0; e8 < 8; e8++) {
        int e = warp * 8 + e8;
        const float4* w = (const float4*)(rw + (long long)e * D_);
        float a0 = 0.f, a1 = 0.f, a2 = 0.f, a3 = 0.f;
        for (int j = lane; j < D_ / 4; j += 32) {
            float4 wv = w[j];
            float4 x0 = ((const float4*)sx[0])[j];
            float4 x1 = ((const float4*)sx[1])[j];
            float4 x2 = ((const float4*)sx[2])[j];
            float4 x3 = ((const float4*)sx[3])[j];
            a0 += wv.x * x0.x + wv.y * x0.y + wv.z * x0.z + wv.w * x0.w;
            a1 += wv.x * x1.x + wv.y * x1.y + wv.z * x1.z + wv.w * x1.w;
            a2 += wv.x * x2.x + wv.y * x2.y + wv.z * x2.z + wv.w * x2.w;
            a3 += wv.x * x3.x + wv.y * x3.y + wv.z * x3.z + wv.w * x3.w;
        }
        #pragma unroll
        for (int off = 16; off > 0; off >>= 1) {
            a0 += __shfl_xor_sync(0xffffffff, a0, off);
            a1 += __shfl_xor_sync(0xffffffff, a1, off);
            a2 += __shfl_xor_sync(0xffffffff, a2, off);
            a3 += __shfl_xor_sync(0xffffffff, a3, off);
        }
        if (lane == 0) {
            slog[0][e] = a0; slog[1][e] = a1; slog[2][e] = a2; slog[3][e] = a3;
        }
    }
    __syncthreads();
    if (tid < 4) {
        const float* lg = slog[tid];
        int t = t0 + tid;
        float mx = -INFINITY;
        for (int e = 0; e < E_; e++) mx = fmaxf(mx, lg[e]);
        float Z = 0.f;
        float v1 = -INFINITY, v2 = -INFINITY;
        int i1 = 0, i2 = 0;
        for (int e = 0; e < E_; e++) {
            float vv = lg[e];
            Z += __expf(vv - mx);
            if (vv > v1) { v2 = v1; i2 = i1; v1 = vv; i1 = e; }
            else if (vv > v2) { v2 = vv; i2 = e; }
        }
        float invZ = 1.f / Z;
        g_top_e[t * 2 + 0] = i1;
        g_top_e[t * 2 + 1] = i2;
        g_top_s[t * 2 + 0] = __expf(v1 - mx) * invZ;
        g_top_s[t * 2 + 1] = __expf(v2 - mx) * invZ;
    }
}

// ---------------- capacity routing: warp-ballot per expert ----------------
__global__ void route_assign_kernel() {
    int warp = threadIdx.x >> 5;
    int lane = threadIdx.x & 31;
    int e = blockIdx.x * (blockDim.x >> 5) + warp;
    if (e >= E_) return;
    int cnt = 0;
    for (int base = 0; base < T_ * TOPK_; base += 32) {
        int idx = base + lane;
        int te = g_top_e[idx];
        unsigned mask = __ballot_sync(0xffffffff, te == e);
        if (te == e) {
            int pos = cnt + __popc(mask & ((1u << lane) - 1));
            if (pos < CAP_) {
                g_dest[idx] = e * CAP_ + pos;
                g_slot_token[e * CAP_ + pos] = idx >> 1;
                g_slot_scale[e * CAP_ + pos] = g_top_s[idx];
            } else {
                g_dest[idx] = -1;
            }
        }
        cnt += __popc(mask);
    }
    if (lane == 0) g_count[e] = cnt < CAP_ ? cnt : CAP_;
}

// ---------------- gather (scaled) into split expert buffers ----------------
__global__ void gather_kernel(const float* __restrict__ hn) {
    int slot = blockIdx.x;
    int e = slot >> 8;
    int p = slot & 255;
    if (p >= g_count[e]) return;
    __nv_bfloat16* dh = g_bufh + (long long)slot * D_;
    __nv_bfloat16* dl = g_bufl + (long long)slot * D_;
    int t = g_slot_token[slot];
    float sc = g_slot_scale[slot];
    const float* src = hn + (long long)t * D_;
    #pragma unroll
    for (int base = 0; base < D_; base += 1024) {
        int d = base + threadIdx.x * 4;
        float4 vv = *(const float4*)(src + d);
        vv.x *= sc; vv.y *= sc; vv.z *= sc; vv.w *= sc;
        uint32_t h01, l01, h23, l23;
        split2(vv.x, vv.y, h01, l01);
        split2(vv.z, vv.w, h23, l23);
        *(uint2*)(dh + d) = make_uint2(h01, h23);
        *(uint2*)(dl + d) = make_uint2(l01, l23);
    }
}

// ---------------- final: out = h + scattered expert outputs ----------------
__global__ void final_kernel(float* __restrict__ out) {
    int t = blockIdx.x;
    int d0 = g_dest[t * 2 + 0];
    int d1 = g_dest[t * 2 + 1];
    const float* hrow = g_h + (long long)t * D_;
    const float* e0 = (d0 >= 0) ? g_eout + (long long)d0 * D_ : nullptr;
    const float* e1 = (d1 >= 0) ? g_eout + (long long)d1 * D_ : nullptr;
    float* orow = out + (long long)t * D_;
    #pragma unroll
    for (int base = 0; base < D_; base += 1024) {
        int d = base + threadIdx.x * 4;
        float4 vv = *(const float4*)(hrow + d);
        if (e0) {
            float4 a = *(const float4*)(e0 + d);
            vv.x += a.x; vv.y += a.y; vv.z += a.z; vv.w += a.w;
        }
        if (e1) {
            float4 a = *(const float4*)(e1 + d);
            vv.x += a.x; vv.y += a.y; vv.z += a.z; vv.w += a.w;
        }
        *(float4*)(orow + d) = vv;
    }
}

// ---------------- host launcher ----------------
template <typename Tp>
static Tp* sym(const void* s) {
    void* p = nullptr;
    cudaGetSymbolAddress(&p, s);
    return (Tp*)p;
}

extern "C" void kernel_launch(void* const* d_in, const int* in_sizes, int n_in,
                              void* d_out, int out_size) {
    const float* x    = (const float*)d_in[0];
    const float* fcos = (const float*)d_in[1];
    const float* fsin = (const float*)d_in[2];
    const float* anw  = (const float*)d_in[3];
    const float* fnw  = (const float*)d_in[4];
    const float* wq   = (const float*)d_in[5];
    const float* wk   = (const float*)d_in[6];
    const float* wv   = (const float*)d_in[7];
    const float* wo   = (const float*)d_in[8];
    const float* rw   = (const float*)d_in[9];
    const float* w1   = (const float*)d_in[10];
    const float* w2   = (const float*)d_in[11];
    const float* w3   = (const float*)d_in[12];
    float* out = (float*)d_out;

    float* h    = sym<float>(g_h);
    float* hn   = sym<float>(g_hn);
    float* eout = sym<float>(g_eout);

    __nv_bfloat16* xnh = sym<__nv_bfloat16>(g_xnh);
    __nv_bfloat16* xnl = sym<__nv_bfloat16>(g_xnl);
    __nv_bfloat16* qh  = sym<__nv_bfloat16>(g_qh);
    __nv_bfloat16* ql  = sym<__nv_bfloat16>(g_ql);
    __nv_bfloat16* kh  = sym<__nv_bfloat16>(g_kh);
    __nv_bfloat16* kl  = sym<__nv_bfloat16>(g_kl);
    __nv_bfloat16* vth = sym<__nv_bfloat16>(g_vth);
    __nv_bfloat16* vtl = sym<__nv_bfloat16>(g_vtl);
    __nv_bfloat16* ath = sym<__nv_bfloat16>(g_ath);
    __nv_bfloat16* atl = sym<__nv_bfloat16>(g_atl);
    __nv_bfloat16* bufh = sym<__nv_bfloat16>(g_bufh);
    __nv_bfloat16* bufl = sym<__nv_bfloat16>(g_bufl);
    __nv_bfloat16* gateh = sym<__nv_bfloat16>(g_gateh);
    __nv_bfloat16* gatel = sym<__nv_bfloat16>(g_gatel);

    cudaFuncSetAttribute(gemm_os<3, 0, 1, 128>, cudaFuncAttributeMaxDynamicSharedMemorySize, GEMM_SMEM_128);
    cudaFuncSetAttribute(gemm_os<1, 0, 0, 128>, cudaFuncAttributeMaxDynamicSharedMemorySize, GEMM_SMEM_128);
    cudaFuncSetAttribute(gemm_os<2, 1, 2, 64>,  cudaFuncAttributeMaxDynamicSharedMemorySize, GEMM_SMEM_64);
    cudaFuncSetAttribute(gemm_os<0, 1, 0, 64>,  cudaFuncAttributeMaxDynamicSharedMemorySize, GEMM_SMEM_64);
    cudaFuncSetAttribute(attn_mma_kernel, cudaFuncAttributeMaxDynamicSharedMemorySize, ATTN_SMEM);

    // 1. attn rmsnorm -> split planes
    rmsnorm_split_kernel<<<S_, 256>>>(x, anw, xnh, xnl);

    // 2. fused qkv projection (raw fp32 weights, on-the-fly split) + rope epilogue
    gemm_os<3, 0, 1, 128><<<dim3(48, 16, 1), 256, GEMM_SMEM_128>>>(
        xnh, xnl, wq, wk, wv, nullptr, nullptr, S_, 3 * D_, D_, 0, 0, 0, fcos, fsin);

    // 3. V transpose + split
    vtrans_kernel<<<dim3(64, 64), dim3(32, 8)>>>(vth, vtl);

    // 4. flash attention -> split planes (double-buffered K/V)
    attn_mma_kernel<<<dim3(32, 16), 128, ATTN_SMEM>>>(qh, ql, kh, kl, vth, vtl, ath, atl);

    // 5. h = x + attn @ wo^T
    gemm_os<1, 0, 0, 128><<<dim3(16, 16, 1), 256, GEMM_SMEM_128>>>(
        ath, atl, wo, nullptr, nullptr, x, h, S_, D_, D_, 0, 0, 0, nullptr, nullptr);

    // 6. ffn rmsnorm
    rmsnorm_kernel<<<S_, 256>>>(h, fnw, hn);

    // 7. router + capacity assignment
    router_topk_kernel<<<T_ / 4, 256>>>(hn, rw);
    route_assign_kernel<<<2, 1024>>>();

    // 8. gather -> split expert buffers (valid slots only)
    gather_kernel<<<E_ * CAP_, 256>>>(hn);

    // 9. expert FFN: 64-row m-tiles, skip tiles >= count
    gemm_os<2, 1, 2, 64><<<dim3(8, 4, E_), 256, GEMM_SMEM_64>>>(
        bufh, bufl, w1, nullptr, w3, nullptr, nullptr,
        CAP_, 2 * HID_, D_,
        (long long)CAP_ * D_, (long long)HID_ * D_, 0, nullptr, nullptr);
    gemm_os<0, 1, 0, 64><<<dim3(16, 4, E_), 256, GEMM_SMEM_64>>>(
        gateh, gatel, w2, nullptr, nullptr, nullptr, eout,
        CAP_, D_, HID_,
        (long long)CAP_ * HID_, (long long)D_ * HID_, (long long)CAP_ * D_, nullptr, nullptr);

    // 10. out = h + scatter(expert outputs)
    final_kernel<<<T_, 256>>>(out);
}

// round 9
// speedup vs baseline: 1.0689x; 1.0689x over previous
#include <cuda_runtime.h>
#include <cuda_bf16.h>
#include <math.h>
#include <stdint.h>

// ---------------- problem constants ----------------
#define S_  2048
#define D_  2048
#define H_  16
#define HD_ 128
#define E_  64
#define TOPK_ 2
#define HID_ 512
#define CAP_ 256
#define T_  (S_)
#define EPS_ 1e-6f
#define QKSCALE_ 0.08838834764831845f

// ---------------- scratch ----------------
__device__ float g_vf  [S_ * D_];
__device__ float g_h   [S_ * D_];
__device__ float g_hn  [S_ * D_];
__device__ int   g_top_e [T_ * TOPK_];
__device__ float g_top_s [T_ * TOPK_];
__device__ int   g_dest  [T_ * TOPK_];
__device__ int   g_count [E_];
__device__ int   g_slot_token[E_ * CAP_];
__device__ float g_slot_scale[E_ * CAP_];
__device__ float g_eout [E_ * CAP_ * D_];

// bf16 split activation planes
__device__ __nv_bfloat16 g_xnh[S_ * D_],  g_xnl[S_ * D_];
__device__ __nv_bfloat16 g_qh [S_ * D_],  g_ql [S_ * D_];
__device__ __nv_bfloat16 g_kh [S_ * D_],  g_kl [S_ * D_];
__device__ __nv_bfloat16 g_vth[D_ * S_],  g_vtl[D_ * S_];
__device__ __nv_bfloat16 g_ath[S_ * D_],  g_atl[S_ * D_];
__device__ __nv_bfloat16 g_bufh[E_ * CAP_ * D_], g_bufl[E_ * CAP_ * D_];
__device__ __nv_bfloat16 g_gateh[E_ * CAP_ * HID_], g_gatel[E_ * CAP_ * HID_];

// ---------------- helpers ----------------
__device__ __forceinline__ void bsplit(float v, __nv_bfloat16& h, __nv_bfloat16& l) {
    h = __float2bfloat16(v);
    l = __float2bfloat16(v - __bfloat162float(h));
}
__device__ __forceinline__ void split2(float x, float y, uint32_t& hi, uint32_t& lo) {
    __nv_bfloat16 hx = __float2bfloat16(x), hy = __float2bfloat16(y);
    __nv_bfloat16 lx = __float2bfloat16(x - __bfloat162float(hx));
    __nv_bfloat16 ly = __float2bfloat16(y - __bfloat162float(hy));
    __nv_bfloat162 hp = __halves2bfloat162(hx, hy);
    __nv_bfloat162 lp = __halves2bfloat162(lx, ly);
    hi = *(uint32_t*)&hp;
    lo = *(uint32_t*)&lp;
}

#define CP_ASYNC16(dst_sm, src_g) \
    asm volatile("cp.async.cg.shared.global [%0], [%1], 16;\n" :: "r"(dst_sm), "l"(src_g))

#define LDSM4(r, ptr) do { \
    uint32_t _a = (uint32_t)__cvta_generic_to_shared(ptr); \
    asm volatile("ldmatrix.sync.aligned.m8n8.x4.shared.b16 {%0,%1,%2,%3}, [%4];\n" \
                 : "=r"((r)[0]), "=r"((r)[1]), "=r"((r)[2]), "=r"((r)[3]) : "r"(_a)); \
} while (0)

#define MMA_BF16(d, a, b0, b1) \
    asm volatile("mma.sync.aligned.m16n8k16.row.col.f32.bf16.bf16.f32 " \
                 "{%0,%1,%2,%3}, {%4,%5,%6,%7}, {%8,%9}, {%0,%1,%2,%3};\n" \
                 : "+f"((d)[0]), "+f"((d)[1]), "+f"((d)[2]), "+f"((d)[3]) \
                 : "r"((a)[0]), "r"((a)[1]), "r"((a)[2]), "r"((a)[3]), "r"(b0), "r"(b1))

// ---------------- RMSNorm variants ----------------
__global__ void rmsnorm_kernel(const float* __restrict__ x,
                               const float* __restrict__ w,
                               float* __restrict__ out) {
    int s = blockIdx.x;
    const float* row = x + (long long)s * D_;
    float ss = 0.f;
    #pragma unroll
    for (int base = 0; base < D_; base += 1024) {
        float4 v = *(const float4*)(row + base + threadIdx.x * 4);
        ss += v.x * v.x + v.y * v.y + v.z * v.z + v.w * v.w;
    }
    __shared__ float red[256];
    red[threadIdx.x] = ss;
    __syncthreads();
    for (int off = 128; off > 0; off >>= 1) {
        if (threadIdx.x < off) red[threadIdx.x] += red[threadIdx.x + off];
        __syncthreads();
    }
    float scale = rsqrtf(red[0] / (float)D_ + EPS_);
    float* orow = out + (long long)s * D_;
    #pragma unroll
    for (int base = 0; base < D_; base += 1024) {
        int d = base + threadIdx.x * 4;
        float4 v = *(const float4*)(row + d);
        float4 ww = *(const float4*)(w + d);
        v.x *= scale * ww.x; v.y *= scale * ww.y;
        v.z *= scale * ww.z; v.w *= scale * ww.w;
        *(float4*)(orow + d) = v;
    }
}

__global__ void rmsnorm_split_kernel(const float* __restrict__ x,
                                     const float* __restrict__ w,
                                     __nv_bfloat16* __restrict__ oh,
                                     __nv_bfloat16* __restrict__ ol) {
    int s = blockIdx.x;
    const float* row = x + (long long)s * D_;
    float ss = 0.f;
    #pragma unroll
    for (int base = 0; base < D_; base += 1024) {
        float4 v = *(const float4*)(row + base + threadIdx.x * 4);
        ss += v.x * v.x + v.y * v.y + v.z * v.z + v.w * v.w;
    }
    __shared__ float red[256];
    red[threadIdx.x] = ss;
    __syncthreads();
    for (int off = 128; off > 0; off >>= 1) {
        if (threadIdx.x < off) red[threadIdx.x] += red[threadIdx.x + off];
        __syncthreads();
    }
    float scale = rsqrtf(red[0] / (float)D_ + EPS_);
    #pragma unroll
    for (int base = 0; base < D_; base += 1024) {
        int d = base + threadIdx.x * 4;
        float4 v = *(const float4*)(row + d);
        float4 ww = *(const float4*)(w + d);
        v.x *= scale * ww.x; v.y *= scale * ww.y;
        v.z *= scale * ww.z; v.w *= scale * ww.w;
        long long off = (long long)s * D_ + d;
        uint32_t h01, l01, h23, l23;
        split2(v.x, v.y, h01, l01);
        split2(v.z, v.w, h23, l23);
        *(uint2*)(oh + off) = make_uint2(h01, h23);
        *(uint2*)(ol + off) = make_uint2(l01, l23);
    }
}

// ---------------- split-free bf16 tensor-core GEMM ----------------
// A: pre-split bf16 planes. B: RAW fp32, converted to frags on the fly.
// MTILE=128: 2-stage, 2 syncs/iter (R7 proven). MTILE=64: 3-stage, 1 sync/iter.
template <int MODE, int SKIP, int BMODE, int MTILE>
__global__ __launch_bounds__(256, 2)
void gemm_os(const __nv_bfloat16* __restrict__ Ah, const __nv_bfloat16* __restrict__ Al,
             const float* __restrict__ B0, const float* __restrict__ B1,
             const float* __restrict__ B2,
             const float* __restrict__ ADD, float* __restrict__ C,
             int M, int N, int K,
             long long sA, long long sB, long long sC,
             const float* __restrict__ fcos, const float* __restrict__ fsin) {
    const int m0 = blockIdx.y * MTILE;
    if (SKIP) {
        if (m0 >= g_count[blockIdx.z]) return;
    }
    constexpr int NST = (MTILE == 64) ? 3 : 2;   // pipeline stages
    constexpr int AST = MTILE * 40;
    constexpr int MF  = MTILE / 32;
    extern __shared__ char smem_raw[];
    __nv_bfloat16* sAh = (__nv_bfloat16*)smem_raw;          // [NST][AST]
    __nv_bfloat16* sAl = sAh + NST * AST;                   // [NST][AST]
    float*         sBf = (float*)(sAl + NST * AST);         // [NST][128*36]

    const __nv_bfloat16* Ahp = Ah + (long long)blockIdx.z * sA;
    const __nv_bfloat16* Alp = Al + (long long)blockIdx.z * sA;
    const long long bzsB = (long long)blockIdx.z * sB;
    C += (long long)blockIdx.z * sC;

    const int tid  = threadIdx.x;
    const int lane = tid & 31;
    const int warp = tid >> 5;
    const int wm = warp & 1;
    const int wn = warp >> 1;
    const int n0 = blockIdx.x * 128;

    float acc[MF][4][4];
    #pragma unroll
    for (int i = 0; i < MF; i++)
        #pragma unroll
        for (int j = 0; j < 4; j++)
            #pragma unroll
            for (int r = 0; r < 4; r++) acc[i][j][r] = 0.f;

    auto copyAB = [&](int stage, int k0) {
        __nv_bfloat16* sa = sAh + stage * AST;
        __nv_bfloat16* sl = sAl + stage * AST;
        #pragma unroll
        for (int i = 0; i < MTILE / 64; i++) {
            int ch  = tid + (i << 8);
            int row = ch >> 2;
            int c   = (ch & 3) << 3;
            const __nv_bfloat16* ap = Ahp + (size_t)(m0 + row) * K + k0 + c;
            const __nv_bfloat16* lp = Alp + (size_t)(m0 + row) * K + k0 + c;
            CP_ASYNC16((uint32_t)__cvta_generic_to_shared(sa + row * 40 + c), ap);
            CP_ASYNC16((uint32_t)__cvta_generic_to_shared(sl + row * 40 + c), lp);
        }
        float* sb = sBf + stage * 4608;
        #pragma unroll
        for (int i = 0; i < 4; i++) {
            int ch  = tid + (i << 8);
            int row = ch >> 3;
            int c   = (ch & 7) << 2;
            int n   = n0 + row;
            const float* src;
            if (BMODE == 0) {
                src = B0 + bzsB + (size_t)n * K;
            } else if (BMODE == 1) {
                int sel = n >> 11;
                const float* w = (sel == 0) ? B0 : ((sel == 1) ? B1 : B2);
                src = w + (size_t)(n & 2047) * K;
            } else {
                const float* w = (n & 1) ? B2 : B0;
                src = w + bzsB + (size_t)(n >> 1) * K;
            }
            CP_ASYNC16((uint32_t)__cvta_generic_to_shared(sb + row * 36 + c), src + k0 + c);
        }
        asm volatile("cp.async.commit_group;\n");
    };

    auto compute = [&](int st) {
        const __nv_bfloat16* sa = sAh + st * AST;
        const __nv_bfloat16* sl = sAl + st * AST;
        const float* sb = sBf + st * 4608;
        #pragma unroll
        for (int ks = 0; ks < 32; ks += 16) {
            uint32_t bh[4][2], bl[4][2];
            const int bn = wn * 32 + (lane >> 2);
            const int bk = ks + ((lane & 3) << 1);
            #pragma unroll
            for (int g = 0; g < 4; g++) {
                const float* p = sb + (bn + g * 8) * 36 + bk;
                float2 x0 = *(const float2*)p;
                float2 x1 = *(const float2*)(p + 8);
                split2(x0.x, x0.y, bh[g][0], bl[g][0]);
                split2(x1.x, x1.y, bh[g][1], bl[g][1]);
            }
            const int ar = lane & 15;
            const int ac = ks + ((lane >> 4) << 3);
            #pragma unroll
            for (int mf = 0; mf < MF; mf++) {
                uint32_t a4[4];
                LDSM4(a4, sa + (wm * (MTILE / 2) + mf * 16 + ar) * 40 + ac);
                #pragma unroll
                for (int nf = 0; nf < 4; nf++)
                    MMA_BF16(acc[mf][nf], a4, bh[nf][0], bh[nf][1]);
                #pragma unroll
                for (int nf = 0; nf < 4; nf++)
                    MMA_BF16(acc[mf][nf], a4, bl[nf][0], bl[nf][1]);
                LDSM4(a4, sl + (wm * (MTILE / 2) + mf * 16 + ar) * 40 + ac);
                #pragma unroll
                for (int nf = 0; nf < 4; nf++)
                    MMA_BF16(acc[mf][nf], a4, bh[nf][0], bh[nf][1]);
            }
        }
    };

    const int KT = K >> 5;
    copyAB(0, 0);
    if (KT > 1) copyAB(1, 32);

    if (NST == 3) {
        // single sync per iter: copy into free stage before compute
        for (int t = 0; t < KT; t++) {
            if (t == KT - 1) {
                asm volatile("cp.async.wait_group 0;\n");
            } else {
                asm volatile("cp.async.wait_group 1;\n");
            }
            __syncthreads();
            if (t + 2 < KT) copyAB((t + 2) % 3, (t + 2) << 5);
            compute(t % 3);
        }
    } else {
        for (int t = 0; t < KT; t++) {
            const int st = t & 1;
            if (t == KT - 1) {
                asm volatile("cp.async.wait_group 0;\n");
            } else {
                asm volatile("cp.async.wait_group 1;\n");
            }
            __syncthreads();
            compute(st);
            __syncthreads();
            if (t + 2 < KT) copyAB(st, (t + 2) << 5);
        }
    }

    const int gq = lane >> 2, th = lane & 3;
    #pragma unroll
    for (int mf = 0; mf < MF; mf++) {
        #pragma unroll
        for (int nf = 0; nf < 4; nf++) {
            int row = m0 + wm * (MTILE / 2) + mf * 16 + gq;
            int col = n0 + wn * 32 + nf * 8 + th * 2;
            float2 v0 = make_float2(acc[mf][nf][0], acc[mf][nf][1]);
            float2 v1 = make_float2(acc[mf][nf][2], acc[mf][nf][3]);
            if (MODE == 0 || MODE == 1) {
                if (MODE == 1) {
                    float2 x0 = *(const float2*)(ADD + (size_t)row * N + col);
                    float2 x1 = *(const float2*)(ADD + (size_t)(row + 8) * N + col);
                    v0.x += x0.x; v0.y += x0.y;
                    v1.x += x1.x; v1.y += x1.y;
                }
                *(float2*)(C + (size_t)row * N + col) = v0;
                *(float2*)(C + (size_t)(row + 8) * N + col) = v1;
            } else if (MODE == 2) {
                int j = col >> 1;
                long long slot0 = (long long)blockIdx.z * CAP_ + row;
                float r0 = v0.x * (1.f / (1.f + __expf(-v0.x))) * v0.y;
                float r1 = v1.x * (1.f / (1.f + __expf(-v1.x))) * v1.y;
                __nv_bfloat16 hb, lb;
                bsplit(r0, hb, lb);
                g_gateh[slot0 * HID_ + j] = hb;
                g_gatel[slot0 * HID_ + j] = lb;
                bsplit(r1, hb, lb);
                g_gateh[(slot0 + 8) * HID_ + j] = hb;
                g_gatel[(slot0 + 8) * HID_ + j] = lb;
            } else {  // MODE 3
                if (col < 2 * D_) {
                    int lc = col & (D_ - 1);
                    int i  = (lc & 127) >> 1;
                    bool isq = col < D_;
                    float sc = isq ? QKSCALE_ : 1.f;
                    __nv_bfloat16* dh = isq ? g_qh : g_kh;
                    __nv_bfloat16* dl = isq ? g_ql : g_kl;
                    float c0 = fcos[row * 64 + i], s0 = fsin[row * 64 + i];
                    float y0 = (v0.x * c0 - v0.y * s0) * sc;
                    float y1 = (v0.x * s0 + v0.y * c0) * sc;
                    uint32_t hi, lo;
                    split2(y0, y1, hi, lo);
                    *(uint32_t*)(dh + (long long)row * D_ + lc) = hi;
                    *(uint32_t*)(dl + (long long)row * D_ + lc) = lo;
                    float c1 = fcos[(row + 8) * 64 + i], s1 = fsin[(row + 8) * 64 + i];
                    y0 = (v1.x * c1 - v1.y * s1) * sc;
                    y1 = (v1.x * s1 + v1.y * c1) * sc;
                    split2(y0, y1, hi, lo);
                    *(uint32_t*)(dh + (long long)(row + 8) * D_ + lc) = hi;
                    *(uint32_t*)(dl + (long long)(row + 8) * D_ + lc) = lo;
                } else {
                    int lc = col - 2 * D_;
                    *(float2*)(g_vf + (long long)row * D_ + lc) = v0;
                    *(float2*)(g_vf + (long long)(row + 8) * D_ + lc) = v1;
                }
            }
        }
    }
}

#define GEMM_SMEM_128 (2 * 2 * (128 * 40) * 2 + 2 * 4608 * 4)   // 77824 B (2-stage)
#define GEMM_SMEM_64  (3 * 2 * (64 * 40) * 2 + 3 * 4608 * 4)    // 86016 B (3-stage)

// ---------------- V transpose + split ----------------
__global__ void vtrans_kernel(__nv_bfloat16* __restrict__ vth,
                              __nv_bfloat16* __restrict__ vtl) {
    __shared__ float tile[32][33];
    int s0 = blockIdx.x * 32;
    int d0 = blockIdx.y * 32;
    int tx = threadIdx.x, ty = threadIdx.y;
    #pragma unroll
    for (int i = 0; i < 4; i++) {
        int r = ty + i * 8;
        tile[r][tx] = g_vf[(long long)(s0 + r) * D_ + d0 + tx];
    }
    __syncthreads();
    #pragma unroll
    for (int i = 0; i < 4; i++) {
        int dr = ty + i * 8;
        float v = tile[tx][dr];
        __nv_bfloat16 hv, lv;
        bsplit(v, hv, lv);
        long long off = (long long)(d0 + dr) * S_ + s0 + tx;
        vth[off] = hv;
        vtl[off] = lv;
    }
}

// ---------------- flash attention, bf16-split mma (R7 proven config) -------
#define ATTN_SMEM 106496
__global__ __launch_bounds__(128)
void attn_mma_kernel(const __nv_bfloat16* __restrict__ qh, const __nv_bfloat16* __restrict__ ql,
                     const __nv_bfloat16* __restrict__ kh, const __nv_bfloat16* __restrict__ kl,
                     const __nv_bfloat16* __restrict__ vth, const __nv_bfloat16* __restrict__ vtl,
                     __nv_bfloat16* __restrict__ oh, __nv_bfloat16* __restrict__ ol) {
    extern __shared__ __nv_bfloat16 dsm[];
    __nv_bfloat16* sQh = dsm;
    __nv_bfloat16* sQl = sQh + 64 * 136;
    __nv_bfloat16* sKh = sQl + 64 * 136;
    __nv_bfloat16* sKl = sKh + 64 * 136;
    __nv_bfloat16* sVh = sKl + 64 * 136;
    __nv_bfloat16* sVl = sVh + 128 * 72;

    const int tid  = threadIdx.x;
    const int lane = tid & 31;
    const int warp = tid >> 5;
    const int h  = blockIdx.y;
    const int qb = gridDim.x - 1 - blockIdx.x;
    const int q0 = qb * 64;
    const int row0 = warp * 16;

    for (int c = tid; c < 1024; c += 128) {
        int r = c >> 4, j = (c & 15) << 3;
        long long g = (long long)(q0 + r) * D_ + h * HD_ + j;
        CP_ASYNC16((uint32_t)__cvta_generic_to_shared(sQh + r * 136 + j), qh + g);
        CP_ASYNC16((uint32_t)__cvta_generic_to_shared(sQl + r * 136 + j), ql + g);
    }
    asm volatile("cp.async.commit_group;\n");

    float m0 = -INFINITY, m1 = -INFINITY, l0 = 0.f, l1 = 0.f;
    float o[16][4];
    #pragma unroll
    for (int f = 0; f < 16; f++)
        #pragma unroll
        for (int r = 0; r < 4; r++) o[f][r] = 0.f;

    const int ntiles = qb + 1;
    for (int kt = 0; kt < ntiles; kt++) {
        const int k0 = kt * 64;
        for (int c = tid; c < 1024; c += 128) {
            int r = c >> 4, j = (c & 15) << 3;
            long long g = (long long)(k0 + r) * D_ + h * HD_ + j;
            CP_ASYNC16((uint32_t)__cvta_generic_to_shared(sKh + r * 136 + j), kh + g);
            CP_ASYNC16((uint32_t)__cvta_generic_to_shared(sKl + r * 136 + j), kl + g);
        }
        asm volatile("cp.async.commit_group;\n");
        for (int c = tid; c < 1024; c += 128) {
            int r = c >> 3, j = (c & 7) << 3;
            long long g = (long long)(h * HD_ + r) * S_ + k0 + j;
            CP_ASYNC16((uint32_t)__cvta_generic_to_shared(sVh + r * 72 + j), vth + g);
            CP_ASYNC16((uint32_t)__cvta_generic_to_shared(sVl + r * 72 + j), vtl + g);
        }
        asm volatile("cp.async.commit_group;\n");
        asm volatile("cp.async.wait_group 1;\n");
        __syncthreads();

        float sc[8][4];
        #pragma unroll
        for (int f = 0; f < 8; f++)
            #pragma unroll
            for (int r = 0; r < 4; r++) sc[f][r] = 0.f;

        #pragma unroll
        for (int ks = 0; ks < 8; ks++) {
            uint32_t ah[4], al[4];
            int ar = lane & 15;
            int ac = ks * 16 + ((lane >> 4) << 3);
            LDSM4(ah, sQh + (row0 + ar) * 136 + ac);
            LDSM4(al, sQl + (row0 + ar) * 136 + ac);
            int br = (lane & 7) + ((lane >> 4) << 3);
            int bc = ks * 16 + (((lane >> 3) & 1) << 3);
            #pragma unroll
            for (int g = 0; g < 4; g++) {
                uint32_t bh[4], bl[4];
                LDSM4(bh, sKh + (g * 16 + br) * 136 + bc);
                LDSM4(bl, sKl + (g * 16 + br) * 136 + bc);
                #pragma unroll
                for (int half = 0; half < 2; half++) {
                    int f = g * 2 + half;
                    MMA_BF16(sc[f], ah, bh[half * 2], bh[half * 2 + 1]);
                    MMA_BF16(sc[f], al, bh[half * 2], bh[half * 2 + 1]);
                    MMA_BF16(sc[f], ah, bl[half * 2], bl[half * 2 + 1]);
                }
            }
        }

        asm volatile("cp.async.wait_group 0;\n");
        __syncthreads();

        int qi0 = q0 + row0 + (lane >> 2);
        if (kt == ntiles - 1) {
            #pragma unroll
            for (int f = 0; f < 8; f++) {
                int ki = k0 + f * 8 + 2 * (lane & 3);
                if (ki > qi0)         sc[f][0] = -INFINITY;
                if (ki + 1 > qi0)     sc[f][1] = -INFINITY;
                if (ki > qi0 + 8)     sc[f][2] = -INFINITY;
                if (ki + 1 > qi0 + 8) sc[f][3] = -INFINITY;
            }
        }

        float mx0 = -INFINITY, mx1 = -INFINITY;
        #pragma unroll
        for (int f = 0; f < 8; f++) {
            mx0 = fmaxf(mx0, fmaxf(sc[f][0], sc[f][1]));
            mx1 = fmaxf(mx1, fmaxf(sc[f][2], sc[f][3]));
        }
        mx0 = fmaxf(mx0, __shfl_xor_sync(0xffffffff, mx0, 1));
        mx0 = fmaxf(mx0, __shfl_xor_sync(0xffffffff, mx0, 2));
        mx1 = fmaxf(mx1, __shfl_xor_sync(0xffffffff, mx1, 1));
        mx1 = fmaxf(mx1, __shfl_xor_sync(0xffffffff, mx1, 2));
        float nm0 = fmaxf(m0, mx0), nm1 = fmaxf(m1, mx1);
        float c0 = __expf(m0 - nm0), c1 = __expf(m1 - nm1);
        float rs0 = 0.f, rs1 = 0.f;
        #pragma unroll
        for (int f = 0; f < 8; f++) {
            sc[f][0] = __expf(sc[f][0] - nm0);
            sc[f][1] = __expf(sc[f][1] - nm0);
            sc[f][2] = __expf(sc[f][2] - nm1);
            sc[f][3] = __expf(sc[f][3] - nm1);
            rs0 += sc[f][0] + sc[f][1];
            rs1 += sc[f][2] + sc[f][3];
        }
        rs0 += __shfl_xor_sync(0xffffffff, rs0, 1);
        rs0 += __shfl_xor_sync(0xffffffff, rs0, 2);
        rs1 += __shfl_xor_sync(0xffffffff, rs1, 1);
        rs1 += __shfl_xor_sync(0xffffffff, rs1, 2);
        l0 = l0 * c0 + rs0;
        l1 = l1 * c1 + rs1;
        m0 = nm0; m1 = nm1;
        #pragma unroll
        for (int f = 0; f < 16; f++) {
            o[f][0] *= c0; o[f][1] *= c0;
            o[f][2] *= c1; o[f][3] *= c1;
        }

        #pragma unroll
        for (int ks = 0; ks < 4; ks++) {
            uint32_t ph[4], pl[4];
            split2(sc[2 * ks][0],     sc[2 * ks][1],     ph[0], pl[0]);
            split2(sc[2 * ks][2],     sc[2 * ks][3],     ph[1], pl[1]);
            split2(sc[2 * ks + 1][0], sc[2 * ks + 1][1], ph[2], pl[2]);
            split2(sc[2 * ks + 1][2], sc[2 * ks + 1][3], ph[3], pl[3]);
            int br = (lane & 7) + ((lane >> 4) << 3);
            int bc = ks * 16 + (((lane >> 3) & 1) << 3);
            #pragma unroll
            for (int g = 0; g < 8; g++) {
                uint32_t vbh[4], vbl[4];
                LDSM4(vbh, sVh + (g * 16 + br) * 72 + bc);
                LDSM4(vbl, sVl + (g * 16 + br) * 72 + bc);
                #pragma unroll
                for (int half = 0; half < 2; half++) {
                    int f = g * 2 + half;
                    MMA_BF16(o[f], ph, vbh[half * 2], vbh[half * 2 + 1]);
                    MMA_BF16(o[f], pl, vbh[half * 2], vbh[half * 2 + 1]);
                    MMA_BF16(o[f], ph, vbl[half * 2], vbl[half * 2 + 1]);
                }
            }
        }
        __syncthreads();
    }

    float inv0 = 1.f / l0, inv1 = 1.f / l1;
    int qi0 = q0 + row0 + (lane >> 2);
    int qi1 = qi0 + 8;
    #pragma unroll
    for (int f = 0; f < 16; f++) {
        int gcol = h * HD_ + f * 8 + 2 * (lane & 3);
        uint32_t hi, lo;
        split2(o[f][0] * inv0, o[f][1] * inv0, hi, lo);
        *(uint32_t*)(oh + (long long)qi0 * D_ + gcol) = hi;
        *(uint32_t*)(ol + (long long)qi0 * D_ + gcol) = lo;
        split2(o[f][2] * inv1, o[f][3] * inv1, hi, lo);
        *(uint32_t*)(oh + (long long)qi1 * D_ + gcol) = hi;
        *(uint32_t*)(ol + (long long)qi1 * D_ + gcol) = lo;
    }
}

// ---------------- fused router: logits + softmax + top-2 ----------------
__global__ void router_topk_kernel(const float* __restrict__ hn,
                                   const float* __restrict__ rw) {
    __shared__ float sx[4][D_];
    __shared__ float slog[4][E_];
    int t0 = blockIdx.x * 4;
    int tid = threadIdx.x;
    for (int c = tid; c < 4 * (D_ / 4); c += 256) {
        int tok = c >> 9;
        int j = c & 511;
        ((float4*)sx[tok])[j] = ((const float4*)(hn + (long long)(t0 + tok) * D_))[j];
    }
    __syncthreads();
    int warp = tid >> 5, lane = tid & 31;
    for (int e8 = 0; e8 < 8; e8++) {
        int e = warp * 8 + e8;
        const float4* w = (const float4*)(rw + (long long)e * D_);
        float a0 = 0.f, a1 = 0.f, a2 = 0.f, a3 = 0.f;
        for (int j = lane; j < D_ / 4; j += 32) {
            float4 wv = w[j];
            float4 x0 = ((const float4*)sx[0])[j];
            float4 x1 = ((const float4*)sx[1])[j];
            float4 x2 = ((const float4*)sx[2])[j];
            float4 x3 = ((const float4*)sx[3])[j];
            a0 += wv.x * x0.x + wv.y * x0.y + wv.z * x0.z + wv.w * x0.w;
            a1 += wv.x * x1.x + wv.y * x1.y + wv.z * x1.z + wv.w * x1.w;
            a2 += wv.x * x2.x + wv.y * x2.y + wv.z * x2.z + wv.w * x2.w;
            a3 += wv.x * x3.x + wv.y * x3.y + wv.z * x3.z + wv.w * x3.w;
        }
        #pragma unroll
        for (int off = 16; off > 0; off >>= 1) {
            a0 += __shfl_xor_sync(0xffffffff, a0, off);
            a1 += __shfl_xor_sync(0xffffffff, a1, off);
            a2 += __shfl_xor_sync(0xffffffff, a2, off);
            a3 += __shfl_xor_sync(0xffffffff, a3, off);
        }
        if (lane == 0) {
            slog[0][e] = a0; slog[1][e] = a1; slog[2][e] = a2; slog[3][e] = a3;
        }
    }
    __syncthreads();
    if (tid < 4) {
        const float* lg = slog[tid];
        int t = t0 + tid;
        float mx = -INFINITY;
        for (int e = 0; e < E_; e++) mx = fmaxf(mx, lg[e]);
        float Z = 0.f;
        float v1 = -INFINITY, v2 = -INFINITY;
        int i1 = 0, i2 = 0;
        for (int e = 0; e < E_; e++) {
            float vv = lg[e];
            Z += __expf(vv - mx);
            if (vv > v1) { v2 = v1; i2 = i1; v1 = vv; i1 = e; }
            else if (vv > v2) { v2 = vv; i2 = e; }
        }
        float invZ = 1.f / Z;
        g_top_e[t * 2 + 0] = i1;
        g_top_e[t * 2 + 1] = i2;
        g_top_s[t * 2 + 0] = __expf(v1 - mx) * invZ;
        g_top_s[t * 2 + 1] = __expf(v2 - mx) * invZ;
    }
}

// ---------------- capacity routing: warp-ballot per expert ----------------
__global__ void route_assign_kernel() {
    int warp = threadIdx.x >> 5;
    int lane = threadIdx.x & 31;
    int e = blockIdx.x * (blockDim.x >> 5) + warp;
    if (e >= E_) return;
    int cnt = 0;
    for (int base = 0; base < T_ * TOPK_; base += 32) {
        int idx = base + lane;
        int te = g_top_e[idx];
        unsigned mask = __ballot_sync(0xffffffff, te == e);
        if (te == e) {
            int pos = cnt + __popc(mask & ((1u << lane) - 1));
            if (pos < CAP_) {
                g_dest[idx] = e * CAP_ + pos;
                g_slot_token[e * CAP_ + pos] = idx >> 1;
                g_slot_scale[e * CAP_ + pos] = g_top_s[idx];
            } else {
                g_dest[idx] = -1;
            }
        }
        cnt += __popc(mask);
    }
    if (lane == 0) g_count[e] = cnt < CAP_ ? cnt : CAP_;
}

// ---------------- gather (scaled) into split expert buffers ----------------
__global__ void gather_kernel(const float* __restrict__ hn) {
    int slot = blockIdx.x;
    int e = slot >> 8;
    int p = slot & 255;
    if (p >= g_count[e]) return;
    __nv_bfloat16* dh = g_bufh + (long long)slot * D_;
    __nv_bfloat16* dl = g_bufl + (long long)slot * D_;
    int t = g_slot_token[slot];
    float sc = g_slot_scale[slot];
    const float* src = hn + (long long)t * D_;
    #pragma unroll
    for (int base = 0; base < D_; base += 1024) {
        int d = base + threadIdx.x * 4;
        float4 vv = *(const float4*)(src + d);
        vv.x *= sc; vv.y *= sc; vv.z *= sc; vv.w *= sc;
        uint32_t h01, l01, h23, l23;
        split2(vv.x, vv.y, h01, l01);
        split2(vv.z, vv.w, h23, l23);
        *(uint2*)(dh + d) = make_uint2(h01, h23);
        *(uint2*)(dl + d) = make_uint2(l01, l23);
    }
}

// ---------------- final: out = h + scattered expert outputs ----------------
__global__ void final_kernel(float* __restrict__ out) {
    int t = blockIdx.x;
    int d0 = g_dest[t * 2 + 0];
    int d1 = g_dest[t * 2 + 1];
    const float* hrow = g_h + (long long)t * D_;
    const float* e0 = (d0 >= 0) ? g_eout + (long long)d0 * D_ : nullptr;
    const float* e1 = (d1 >= 0) ? g_eout + (long long)d1 * D_ : nullptr;
    float* orow = out + (long long)t * D_;
    #pragma unroll
    for (int base = 0; base < D_; base += 1024) {
        int d = base + threadIdx.x * 4;
        float4 vv = *(const float4*)(hrow + d);
        if (e0) {
            float4 a = *(const float4*)(e0 + d);
            vv.x += a.x; vv.y += a.y; vv.z += a.z; vv.w += a.w;
        }
        if (e1) {
            float4 a = *(const float4*)(e1 + d);
            vv.x += a.x; vv.y += a.y; vv.z += a.z; vv.w += a.w;
        }
        *(float4*)(orow + d) = vv;
    }
}

// ---------------- host launcher ----------------
template <typename Tp>
static Tp* sym(const void* s) {
    void* p = nullptr;
    cudaGetSymbolAddress(&p, s);
    return (Tp*)p;
}

extern "C" void kernel_launch(void* const* d_in, const int* in_sizes, int n_in,
                              void* d_out, int out_size) {
    const float* x    = (const float*)d_in[0];
    const float* fcos = (const float*)d_in[1];
    const float* fsin = (const float*)d_in[2];
    const float* anw  = (const float*)d_in[3];
    const float* fnw  = (const float*)d_in[4];
    const float* wq   = (const float*)d_in[5];
    const float* wk   = (const float*)d_in[6];
    const float* wv   = (const float*)d_in[7];
    const float* wo   = (const float*)d_in[8];
    const float* rw   = (const float*)d_in[9];
    const float* w1   = (const float*)d_in[10];
    const float* w2   = (const float*)d_in[11];
    const float* w3   = (const float*)d_in[12];
    float* out = (float*)d_out;

    float* h    = sym<float>(g_h);
    float* hn   = sym<float>(g_hn);
    float* eout = sym<float>(g_eout);

    __nv_bfloat16* xnh = sym<__nv_bfloat16>(g_xnh);
    __nv_bfloat16* xnl = sym<__nv_bfloat16>(g_xnl);
    __nv_bfloat16* qh  = sym<__nv_bfloat16>(g_qh);
    __nv_bfloat16* ql  = sym<__nv_bfloat16>(g_ql);
    __nv_bfloat16* kh  = sym<__nv_bfloat16>(g_kh);
    __nv_bfloat16* kl  = sym<__nv_bfloat16>(g_kl);
    __nv_bfloat16* vth = sym<__nv_bfloat16>(g_vth);
    __nv_bfloat16* vtl = sym<__nv_bfloat16>(g_vtl);
    __nv_bfloat16* ath = sym<__nv_bfloat16>(g_ath);
    __nv_bfloat16* atl = sym<__nv_bfloat16>(g_atl);
    __nv_bfloat16* bufh = sym<__nv_bfloat16>(g_bufh);
    __nv_bfloat16* bufl = sym<__nv_bfloat16>(g_bufl);
    __nv_bfloat16* gateh = sym<__nv_bfloat16>(g_gateh);
    __nv_bfloat16* gatel = sym<__nv_bfloat16>(g_gatel);

    cudaFuncSetAttribute(gemm_os<3, 0, 1, 128>, cudaFuncAttributeMaxDynamicSharedMemorySize, GEMM_SMEM_128);
    cudaFuncSetAttribute(gemm_os<1, 0, 0, 128>, cudaFuncAttributeMaxDynamicSharedMemorySize, GEMM_SMEM_128);
    cudaFuncSetAttribute(gemm_os<2, 1, 2, 64>,  cudaFuncAttributeMaxDynamicSharedMemorySize, GEMM_SMEM_64);
    cudaFuncSetAttribute(gemm_os<0, 1, 0, 64>,  cudaFuncAttributeMaxDynamicSharedMemorySize, GEMM_SMEM_64);
    cudaFuncSetAttribute(attn_mma_kernel, cudaFuncAttributeMaxDynamicSharedMemorySize, ATTN_SMEM);

    // 1. attn rmsnorm -> split planes
    rmsnorm_split_kernel<<<S_, 256>>>(x, anw, xnh, xnl);

    // 2. fused qkv projection (raw fp32 weights, on-the-fly split) + rope epilogue
    gemm_os<3, 0, 1, 128><<<dim3(48, 16, 1), 256, GEMM_SMEM_128>>>(
        xnh, xnl, wq, wk, wv, nullptr, nullptr, S_, 3 * D_, D_, 0, 0, 0, fcos, fsin);

    // 3. V transpose + split
    vtrans_kernel<<<dim3(64, 64), dim3(32, 8)>>>(vth, vtl);

    // 4. flash attention -> split planes (R7 config: 2 CTAs/SM)
    attn_mma_kernel<<<dim3(32, 16), 128, ATTN_SMEM>>>(qh, ql, kh, kl, vth, vtl, ath, atl);

    // 5. h = x + attn @ wo^T
    gemm_os<1, 0, 0, 128><<<dim3(16, 16, 1), 256, GEMM_SMEM_128>>>(
        ath, atl, wo, nullptr, nullptr, x, h, S_, D_, D_, 0, 0, 0, nullptr, nullptr);

    // 6. ffn rmsnorm
    rmsnorm_kernel<<<S_, 256>>>(h, fnw, hn);

    // 7. router + capacity assignment
    router_topk_kernel<<<T_ / 4, 256>>>(hn, rw);
    route_assign_kernel<<<2, 1024>>>();

    // 8. gather -> split expert buffers (valid slots only)
    gather_kernel<<<E_ * CAP_, 256>>>(hn);

    // 9. expert FFN: 64-row m-tiles (3-stage pipeline), skip tiles >= count
    gemm_os<2, 1, 2, 64><<<dim3(8, 4, E_), 256, GEMM_SMEM_64>>>(
        bufh, bufl, w1, nullptr, w3, nullptr, nullptr,
        CAP_, 2 * HID_, D_,
        (long long)CAP_ * D_, (long long)HID_ * D_, 0, nullptr, nullptr);
    gemm_os<0, 1, 0, 64><<<dim3(16, 4, E_), 256, GEMM_SMEM_64>>>(
        gateh, gatel, w2, nullptr, nullptr, nullptr, eout,
        CAP_, D_, HID_,
        (long long)CAP_ * HID_, (long long)D_ * HID_, (long long)CAP_ * D_, nullptr, nullptr);

    // 10. out = h + scatter(expert outputs)
    final_kernel<<<T_, 256>>>(out);
}

// round 10
// speedup vs baseline: 1.0705x; 1.0015x over previous
#include <cuda_runtime.h>
#include <cuda_bf16.h>
#include <math.h>
#include <stdint.h>

// ---------------- problem constants ----------------
#define S_  2048
#define D_  2048
#define H_  16
#define HD_ 128
#define E_  64
#define TOPK_ 2
#define HID_ 512
#define CAP_ 256
#define T_  (S_)
#define EPS_ 1e-6f
#define QKSCALE_ 0.08838834764831845f

// ---------------- scratch ----------------
__device__ float g_vf  [S_ * D_];
__device__ float g_h   [S_ * D_];
__device__ float g_hn  [S_ * D_];
__device__ int   g_top_e [T_ * TOPK_];
__device__ float g_top_s [T_ * TOPK_];
__device__ int   g_dest  [T_ * TOPK_];
__device__ int   g_count [E_];
__device__ int   g_slot_token[E_ * CAP_];
__device__ float g_slot_scale[E_ * CAP_];
__device__ float g_eout [E_ * CAP_ * D_];

// bf16 split activation planes
__device__ __nv_bfloat16 g_xnh[S_ * D_],  g_xnl[S_ * D_];
__device__ __nv_bfloat16 g_qh [S_ * D_],  g_ql [S_ * D_];
__device__ __nv_bfloat16 g_kh [S_ * D_],  g_kl [S_ * D_];
__device__ __nv_bfloat16 g_vth[D_ * S_],  g_vtl[D_ * S_];
__device__ __nv_bfloat16 g_ath[S_ * D_],  g_atl[S_ * D_];
__device__ __nv_bfloat16 g_bufh[E_ * CAP_ * D_], g_bufl[E_ * CAP_ * D_];
__device__ __nv_bfloat16 g_gateh[E_ * CAP_ * HID_], g_gatel[E_ * CAP_ * HID_];

// ---------------- helpers ----------------
__device__ __forceinline__ void bsplit(float v, __nv_bfloat16& h, __nv_bfloat16& l) {
    h = __float2bfloat16(v);
    l = __float2bfloat16(v - __bfloat162float(h));
}
__device__ __forceinline__ void split2(float x, float y, uint32_t& hi, uint32_t& lo) {
    __nv_bfloat16 hx = __float2bfloat16(x), hy = __float2bfloat16(y);
    __nv_bfloat16 lx = __float2bfloat16(x - __bfloat162float(hx));
    __nv_bfloat16 ly = __float2bfloat16(y - __bfloat162float(hy));
    __nv_bfloat162 hp = __halves2bfloat162(hx, hy);
    __nv_bfloat162 lp = __halves2bfloat162(lx, ly);
    hi = *(uint32_t*)&hp;
    lo = *(uint32_t*)&lp;
}

#define CP_ASYNC16(dst_sm, src_g) \
    asm volatile("cp.async.cg.shared.global [%0], [%1], 16;\n" :: "r"(dst_sm), "l"(src_g))

#define LDSM4(r, ptr) do { \
    uint32_t _a = (uint32_t)__cvta_generic_to_shared(ptr); \
    asm volatile("ldmatrix.sync.aligned.m8n8.x4.shared.b16 {%0,%1,%2,%3}, [%4];\n" \
                 : "=r"((r)[0]), "=r"((r)[1]), "=r"((r)[2]), "=r"((r)[3]) : "r"(_a)); \
} while (0)

#define MMA_BF16(d, a, b0, b1) \
    asm volatile("mma.sync.aligned.m16n8k16.row.col.f32.bf16.bf16.f32 " \
                 "{%0,%1,%2,%3}, {%4,%5,%6,%7}, {%8,%9}, {%0,%1,%2,%3};\n" \
                 : "+f"((d)[0]), "+f"((d)[1]), "+f"((d)[2]), "+f"((d)[3]) \
                 : "r"((a)[0]), "r"((a)[1]), "r"((a)[2]), "r"((a)[3]), "r"(b0), "r"(b1))

// ---------------- RMSNorm variants ----------------
__global__ void rmsnorm_kernel(const float* __restrict__ x,
                               const float* __restrict__ w,
                               float* __restrict__ out) {
    int s = blockIdx.x;
    const float* row = x + (long long)s * D_;
    float ss = 0.f;
    #pragma unroll
    for (int base = 0; base < D_; base += 1024) {
        float4 v = *(const float4*)(row + base + threadIdx.x * 4);
        ss += v.x * v.x + v.y * v.y + v.z * v.z + v.w * v.w;
    }
    __shared__ float red[256];
    red[threadIdx.x] = ss;
    __syncthreads();
    for (int off = 128; off > 0; off >>= 1) {
        if (threadIdx.x < off) red[threadIdx.x] += red[threadIdx.x + off];
        __syncthreads();
    }
    float scale = rsqrtf(red[0] / (float)D_ + EPS_);
    float* orow = out + (long long)s * D_;
    #pragma unroll
    for (int base = 0; base < D_; base += 1024) {
        int d = base + threadIdx.x * 4;
        float4 v = *(const float4*)(row + d);
        float4 ww = *(const float4*)(w + d);
        v.x *= scale * ww.x; v.y *= scale * ww.y;
        v.z *= scale * ww.z; v.w *= scale * ww.w;
        *(float4*)(orow + d) = v;
    }
}

__global__ void rmsnorm_split_kernel(const float* __restrict__ x,
                                     const float* __restrict__ w,
                                     __nv_bfloat16* __restrict__ oh,
                                     __nv_bfloat16* __restrict__ ol) {
    int s = blockIdx.x;
    const float* row = x + (long long)s * D_;
    float ss = 0.f;
    #pragma unroll
    for (int base = 0; base < D_; base += 1024) {
        float4 v = *(const float4*)(row + base + threadIdx.x * 4);
        ss += v.x * v.x + v.y * v.y + v.z * v.z + v.w * v.w;
    }
    __shared__ float red[256];
    red[threadIdx.x] = ss;
    __syncthreads();
    for (int off = 128; off > 0; off >>= 1) {
        if (threadIdx.x < off) red[threadIdx.x] += red[threadIdx.x + off];
        __syncthreads();
    }
    float scale = rsqrtf(red[0] / (float)D_ + EPS_);
    #pragma unroll
    for (int base = 0; base < D_; base += 1024) {
        int d = base + threadIdx.x * 4;
        float4 v = *(const float4*)(row + d);
        float4 ww = *(const float4*)(w + d);
        v.x *= scale * ww.x; v.y *= scale * ww.y;
        v.z *= scale * ww.z; v.w *= scale * ww.w;
        long long off = (long long)s * D_ + d;
        uint32_t h01, l01, h23, l23;
        split2(v.x, v.y, h01, l01);
        split2(v.z, v.w, h23, l23);
        *(uint2*)(oh + off) = make_uint2(h01, h23);
        *(uint2*)(ol + off) = make_uint2(l01, l23);
    }
}

// ---------------- split-free bf16 tensor-core GEMM (R9 config) --------------
template <int MODE, int SKIP, int BMODE, int MTILE>
__global__ __launch_bounds__(256, 2)
void gemm_os(const __nv_bfloat16* __restrict__ Ah, const __nv_bfloat16* __restrict__ Al,
             const float* __restrict__ B0, const float* __restrict__ B1,
             const float* __restrict__ B2,
             const float* __restrict__ ADD, float* __restrict__ C,
             int M, int N, int K,
             long long sA, long long sB, long long sC,
             const float* __restrict__ fcos, const float* __restrict__ fsin) {
    const int m0 = blockIdx.y * MTILE;
    if (SKIP) {
        if (m0 >= g_count[blockIdx.z]) return;
    }
    constexpr int NST = (MTILE == 64) ? 3 : 2;
    constexpr int AST = MTILE * 40;
    constexpr int MF  = MTILE / 32;
    extern __shared__ char smem_raw[];
    __nv_bfloat16* sAh = (__nv_bfloat16*)smem_raw;
    __nv_bfloat16* sAl = sAh + NST * AST;
    float*         sBf = (float*)(sAl + NST * AST);

    const __nv_bfloat16* Ahp = Ah + (long long)blockIdx.z * sA;
    const __nv_bfloat16* Alp = Al + (long long)blockIdx.z * sA;
    const long long bzsB = (long long)blockIdx.z * sB;
    C += (long long)blockIdx.z * sC;

    const int tid  = threadIdx.x;
    const int lane = tid & 31;
    const int warp = tid >> 5;
    const int wm = warp & 1;
    const int wn = warp >> 1;
    const int n0 = blockIdx.x * 128;

    float acc[MF][4][4];
    #pragma unroll
    for (int i = 0; i < MF; i++)
        #pragma unroll
        for (int j = 0; j < 4; j++)
            #pragma unroll
            for (int r = 0; r < 4; r++) acc[i][j][r] = 0.f;

    auto copyAB = [&](int stage, int k0) {
        __nv_bfloat16* sa = sAh + stage * AST;
        __nv_bfloat16* sl = sAl + stage * AST;
        #pragma unroll
        for (int i = 0; i < MTILE / 64; i++) {
            int ch  = tid + (i << 8);
            int row = ch >> 2;
            int c   = (ch & 3) << 3;
            const __nv_bfloat16* ap = Ahp + (size_t)(m0 + row) * K + k0 + c;
            const __nv_bfloat16* lp = Alp + (size_t)(m0 + row) * K + k0 + c;
            CP_ASYNC16((uint32_t)__cvta_generic_to_shared(sa + row * 40 + c), ap);
            CP_ASYNC16((uint32_t)__cvta_generic_to_shared(sl + row * 40 + c), lp);
        }
        float* sb = sBf + stage * 4608;
        #pragma unroll
        for (int i = 0; i < 4; i++) {
            int ch  = tid + (i << 8);
            int row = ch >> 3;
            int c   = (ch & 7) << 2;
            int n   = n0 + row;
            const float* src;
            if (BMODE == 0) {
                src = B0 + bzsB + (size_t)n * K;
            } else if (BMODE == 1) {
                int sel = n >> 11;
                const float* w = (sel == 0) ? B0 : ((sel == 1) ? B1 : B2);
                src = w + (size_t)(n & 2047) * K;
            } else {
                const float* w = (n & 1) ? B2 : B0;
                src = w + bzsB + (size_t)(n >> 1) * K;
            }
            CP_ASYNC16((uint32_t)__cvta_generic_to_shared(sb + row * 36 + c), src + k0 + c);
        }
        asm volatile("cp.async.commit_group;\n");
    };

    auto compute = [&](int st) {
        const __nv_bfloat16* sa = sAh + st * AST;
        const __nv_bfloat16* sl = sAl + st * AST;
        const float* sb = sBf + st * 4608;
        #pragma unroll
        for (int ks = 0; ks < 32; ks += 16) {
            uint32_t bh[4][2], bl[4][2];
            const int bn = wn * 32 + (lane >> 2);
            const int bk = ks + ((lane & 3) << 1);
            #pragma unroll
            for (int g = 0; g < 4; g++) {
                const float* p = sb + (bn + g * 8) * 36 + bk;
                float2 x0 = *(const float2*)p;
                float2 x1 = *(const float2*)(p + 8);
                split2(x0.x, x0.y, bh[g][0], bl[g][0]);
                split2(x1.x, x1.y, bh[g][1], bl[g][1]);
            }
            const int ar = lane & 15;
            const int ac = ks + ((lane >> 4) << 3);
            #pragma unroll
            for (int mf = 0; mf < MF; mf++) {
                uint32_t a4[4];
                LDSM4(a4, sa + (wm * (MTILE / 2) + mf * 16 + ar) * 40 + ac);
                #pragma unroll
                for (int nf = 0; nf < 4; nf++)
                    MMA_BF16(acc[mf][nf], a4, bh[nf][0], bh[nf][1]);
                #pragma unroll
                for (int nf = 0; nf < 4; nf++)
                    MMA_BF16(acc[mf][nf], a4, bl[nf][0], bl[nf][1]);
                LDSM4(a4, sl + (wm * (MTILE / 2) + mf * 16 + ar) * 40 + ac);
                #pragma unroll
                for (int nf = 0; nf < 4; nf++)
                    MMA_BF16(acc[mf][nf], a4, bh[nf][0], bh[nf][1]);
            }
        }
    };

    const int KT = K >> 5;
    copyAB(0, 0);
    if (KT > 1) copyAB(1, 32);

    if (NST == 3) {
        for (int t = 0; t < KT; t++) {
            if (t == KT - 1) {
                asm volatile("cp.async.wait_group 0;\n");
            } else {
                asm volatile("cp.async.wait_group 1;\n");
            }
            __syncthreads();
            if (t + 2 < KT) copyAB((t + 2) % 3, (t + 2) << 5);
            compute(t % 3);
        }
    } else {
        for (int t = 0; t < KT; t++) {
            const int st = t & 1;
            if (t == KT - 1) {
                asm volatile("cp.async.wait_group 0;\n");
            } else {
                asm volatile("cp.async.wait_group 1;\n");
            }
            __syncthreads();
            compute(st);
            __syncthreads();
            if (t + 2 < KT) copyAB(st, (t + 2) << 5);
        }
    }

    const int gq = lane >> 2, th = lane & 3;
    #pragma unroll
    for (int mf = 0; mf < MF; mf++) {
        #pragma unroll
        for (int nf = 0; nf < 4; nf++) {
            int row = m0 + wm * (MTILE / 2) + mf * 16 + gq;
            int col = n0 + wn * 32 + nf * 8 + th * 2;
            float2 v0 = make_float2(acc[mf][nf][0], acc[mf][nf][1]);
            float2 v1 = make_float2(acc[mf][nf][2], acc[mf][nf][3]);
            if (MODE == 0 || MODE == 1) {
                if (MODE == 1) {
                    float2 x0 = *(const float2*)(ADD + (size_t)row * N + col);
                    float2 x1 = *(const float2*)(ADD + (size_t)(row + 8) * N + col);
                    v0.x += x0.x; v0.y += x0.y;
                    v1.x += x1.x; v1.y += x1.y;
                }
                *(float2*)(C + (size_t)row * N + col) = v0;
                *(float2*)(C + (size_t)(row + 8) * N + col) = v1;
            } else if (MODE == 2) {
                int j = col >> 1;
                long long slot0 = (long long)blockIdx.z * CAP_ + row;
                float r0 = v0.x * (1.f / (1.f + __expf(-v0.x))) * v0.y;
                float r1 = v1.x * (1.f / (1.f + __expf(-v1.x))) * v1.y;
                __nv_bfloat16 hb, lb;
                bsplit(r0, hb, lb);
                g_gateh[slot0 * HID_ + j] = hb;
                g_gatel[slot0 * HID_ + j] = lb;
                bsplit(r1, hb, lb);
                g_gateh[(slot0 + 8) * HID_ + j] = hb;
                g_gatel[(slot0 + 8) * HID_ + j] = lb;
            } else {  // MODE 3
                if (col < 2 * D_) {
                    int lc = col & (D_ - 1);
                    int i  = (lc & 127) >> 1;
                    bool isq = col < D_;
                    float sc = isq ? QKSCALE_ : 1.f;
                    __nv_bfloat16* dh = isq ? g_qh : g_kh;
                    __nv_bfloat16* dl = isq ? g_ql : g_kl;
                    float c0 = fcos[row * 64 + i], s0 = fsin[row * 64 + i];
                    float y0 = (v0.x * c0 - v0.y * s0) * sc;
                    float y1 = (v0.x * s0 + v0.y * c0) * sc;
                    uint32_t hi, lo;
                    split2(y0, y1, hi, lo);
                    *(uint32_t*)(dh + (long long)row * D_ + lc) = hi;
                    *(uint32_t*)(dl + (long long)row * D_ + lc) = lo;
                    float c1 = fcos[(row + 8) * 64 + i], s1 = fsin[(row + 8) * 64 + i];
                    y0 = (v1.x * c1 - v1.y * s1) * sc;
                    y1 = (v1.x * s1 + v1.y * c1) * sc;
                    split2(y0, y1, hi, lo);
                    *(uint32_t*)(dh + (long long)(row + 8) * D_ + lc) = hi;
                    *(uint32_t*)(dl + (long long)(row + 8) * D_ + lc) = lo;
                } else {
                    int lc = col - 2 * D_;
                    *(float2*)(g_vf + (long long)row * D_ + lc) = v0;
                    *(float2*)(g_vf + (long long)(row + 8) * D_ + lc) = v1;
                }
            }
        }
    }
}

#define GEMM_SMEM_128 (2 * 2 * (128 * 40) * 2 + 2 * 4608 * 4)   // 77824 B (2-stage)
#define GEMM_SMEM_64  (3 * 2 * (64 * 40) * 2 + 3 * 4608 * 4)    // 86016 B (3-stage)

// ---------------- V transpose + split ----------------
__global__ void vtrans_kernel(__nv_bfloat16* __restrict__ vth,
                              __nv_bfloat16* __restrict__ vtl) {
    __shared__ float tile[32][33];
    int s0 = blockIdx.x * 32;
    int d0 = blockIdx.y * 32;
    int tx = threadIdx.x, ty = threadIdx.y;
    #pragma unroll
    for (int i = 0; i < 4; i++) {
        int r = ty + i * 8;
        tile[r][tx] = g_vf[(long long)(s0 + r) * D_ + d0 + tx];
    }
    __syncthreads();
    #pragma unroll
    for (int i = 0; i < 4; i++) {
        int dr = ty + i * 8;
        float v = tile[tx][dr];
        __nv_bfloat16 hv, lv;
        bsplit(v, hv, lv);
        long long off = (long long)(d0 + dr) * S_ + s0 + tx;
        vth[off] = hv;
        vtl[off] = lv;
    }
}

// ---------------- flash attention, 32-key tiles, 3 CTAs/SM ----------------
// 64 queries x 1 head, 128 threads (4 warps), key tiles of 32.
#define ATTN_SMEM ((2 * 64 * 136 + 2 * 32 * 136 + 2 * 128 * 40) * 2)   // 72704 B
__global__ __launch_bounds__(128, 3)
void attn_mma_kernel(const __nv_bfloat16* __restrict__ qh, const __nv_bfloat16* __restrict__ ql,
                     const __nv_bfloat16* __restrict__ kh, const __nv_bfloat16* __restrict__ kl,
                     const __nv_bfloat16* __restrict__ vth, const __nv_bfloat16* __restrict__ vtl,
                     __nv_bfloat16* __restrict__ oh, __nv_bfloat16* __restrict__ ol) {
    extern __shared__ __nv_bfloat16 dsm[];
    __nv_bfloat16* sQh = dsm;                   // [64][136]
    __nv_bfloat16* sQl = sQh + 64 * 136;
    __nv_bfloat16* sKh = sQl + 64 * 136;        // [32][136]
    __nv_bfloat16* sKl = sKh + 32 * 136;
    __nv_bfloat16* sVh = sKl + 32 * 136;        // [128][40]
    __nv_bfloat16* sVl = sVh + 128 * 40;

    const int tid  = threadIdx.x;
    const int lane = tid & 31;
    const int warp = tid >> 5;
    const int h  = blockIdx.y;
    const int qb = gridDim.x - 1 - blockIdx.x;
    const int q0 = qb * 64;
    const int row0 = warp * 16;

    // Q tile (persists) — group 0
    for (int c = tid; c < 1024; c += 128) {
        int r = c >> 4, j = (c & 15) << 3;
        long long g = (long long)(q0 + r) * D_ + h * HD_ + j;
        CP_ASYNC16((uint32_t)__cvta_generic_to_shared(sQh + r * 136 + j), qh + g);
        CP_ASYNC16((uint32_t)__cvta_generic_to_shared(sQl + r * 136 + j), ql + g);
    }
    asm volatile("cp.async.commit_group;\n");

    float m0 = -INFINITY, m1 = -INFINITY, l0 = 0.f, l1 = 0.f;
    float o[16][4];
    #pragma unroll
    for (int f = 0; f < 16; f++)
        #pragma unroll
        for (int r = 0; r < 4; r++) o[f][r] = 0.f;

    const int ntiles = 2 * qb + 2;
    for (int kt = 0; kt < ntiles; kt++) {
        const int k0 = kt * 32;
        // K tile (32 keys), own group
        for (int c = tid; c < 512; c += 128) {
            int r = c >> 4, j = (c & 15) << 3;
            long long g = (long long)(k0 + r) * D_ + h * HD_ + j;
            CP_ASYNC16((uint32_t)__cvta_generic_to_shared(sKh + r * 136 + j), kh + g);
            CP_ASYNC16((uint32_t)__cvta_generic_to_shared(sKl + r * 136 + j), kl + g);
        }
        asm volatile("cp.async.commit_group;\n");
        // V tile (32 keys), second group
        for (int c = tid; c < 512; c += 128) {
            int r = c >> 2, j = (c & 3) << 3;
            long long g = (long long)(h * HD_ + r) * S_ + k0 + j;
            CP_ASYNC16((uint32_t)__cvta_generic_to_shared(sVh + r * 40 + j), vth + g);
            CP_ASYNC16((uint32_t)__cvta_generic_to_shared(sVl + r * 40 + j), vtl + g);
        }
        asm volatile("cp.async.commit_group;\n");
        asm volatile("cp.async.wait_group 1;\n");
        __syncthreads();

        float sc[4][4];
        #pragma unroll
        for (int f = 0; f < 4; f++)
            #pragma unroll
            for (int r = 0; r < 4; r++) sc[f][r] = 0.f;

        #pragma unroll
        for (int ks = 0; ks < 8; ks++) {
            uint32_t ah[4], al[4];
            int ar = lane & 15;
            int ac = ks * 16 + ((lane >> 4) << 3);
            LDSM4(ah, sQh + (row0 + ar) * 136 + ac);
            LDSM4(al, sQl + (row0 + ar) * 136 + ac);
            int br = (lane & 7) + ((lane >> 4) << 3);
            int bc = ks * 16 + (((lane >> 3) & 1) << 3);
            #pragma unroll
            for (int g = 0; g < 2; g++) {
                uint32_t bh[4], bl[4];
                LDSM4(bh, sKh + (g * 16 + br) * 136 + bc);
                LDSM4(bl, sKl + (g * 16 + br) * 136 + bc);
                #pragma unroll
                for (int half = 0; half < 2; half++) {
                    int f = g * 2 + half;
                    MMA_BF16(sc[f], ah, bh[half * 2], bh[half * 2 + 1]);
                    MMA_BF16(sc[f], al, bh[half * 2], bh[half * 2 + 1]);
                    MMA_BF16(sc[f], ah, bl[half * 2], bl[half * 2 + 1]);
                }
            }
        }

        asm volatile("cp.async.wait_group 0;\n");
        __syncthreads();

        int qi0 = q0 + row0 + (lane >> 2);
        if (k0 + 31 > q0 + row0) {      // diagonal region for this warp
            #pragma unroll
            for (int f = 0; f < 4; f++) {
                int ki = k0 + f * 8 + 2 * (lane & 3);
                if (ki > qi0)         sc[f][0] = -INFINITY;
                if (ki + 1 > qi0)     sc[f][1] = -INFINITY;
                if (ki > qi0 + 8)     sc[f][2] = -INFINITY;
                if (ki + 1 > qi0 + 8) sc[f][3] = -INFINITY;
            }
        }

        float mx0 = -INFINITY, mx1 = -INFINITY;
        #pragma unroll
        for (int f = 0; f < 4; f++) {
            mx0 = fmaxf(mx0, fmaxf(sc[f][0], sc[f][1]));
            mx1 = fmaxf(mx1, fmaxf(sc[f][2], sc[f][3]));
        }
        mx0 = fmaxf(mx0, __shfl_xor_sync(0xffffffff, mx0, 1));
        mx0 = fmaxf(mx0, __shfl_xor_sync(0xffffffff, mx0, 2));
        mx1 = fmaxf(mx1, __shfl_xor_sync(0xffffffff, mx1, 1));
        mx1 = fmaxf(mx1, __shfl_xor_sync(0xffffffff, mx1, 2));
        float nm0 = fmaxf(m0, mx0), nm1 = fmaxf(m1, mx1);
        float c0 = __expf(m0 - nm0), c1 = __expf(m1 - nm1);
        float rs0 = 0.f, rs1 = 0.f;
        #pragma unroll
        for (int f = 0; f < 4; f++) {
            sc[f][0] = __expf(sc[f][0] - nm0);
            sc[f][1] = __expf(sc[f][1] - nm0);
            sc[f][2] = __expf(sc[f][2] - nm1);
            sc[f][3] = __expf(sc[f][3] - nm1);
            rs0 += sc[f][0] + sc[f][1];
            rs1 += sc[f][2] + sc[f][3];
        }
        rs0 += __shfl_xor_sync(0xffffffff, rs0, 1);
        rs0 += __shfl_xor_sync(0xffffffff, rs0, 2);
        rs1 += __shfl_xor_sync(0xffffffff, rs1, 1);
        rs1 += __shfl_xor_sync(0xffffffff, rs1, 2);
        l0 = l0 * c0 + rs0;
        l1 = l1 * c1 + rs1;
        m0 = nm0; m1 = nm1;
        #pragma unroll
        for (int f = 0; f < 16; f++) {
            o[f][0] *= c0; o[f][1] *= c0;
            o[f][2] *= c1; o[f][3] *= c1;
        }

        // P·V over 32-key chunk
        #pragma unroll
        for (int ks = 0; ks < 2; ks++) {
            uint32_t ph[4], pl[4];
            split2(sc[2 * ks][0],     sc[2 * ks][1],     ph[0], pl[0]);
            split2(sc[2 * ks][2],     sc[2 * ks][3],     ph[1], pl[1]);
            split2(sc[2 * ks + 1][0], sc[2 * ks + 1][1], ph[2], pl[2]);
            split2(sc[2 * ks + 1][2], sc[2 * ks + 1][3], ph[3], pl[3]);
            int br = (lane & 7) + ((lane >> 4) << 3);
            int bc = ks * 16 + (((lane >> 3) & 1) << 3);
            #pragma unroll
            for (int g = 0; g < 8; g++) {
                uint32_t vbh[4], vbl[4];
                LDSM4(vbh, sVh + (g * 16 + br) * 40 + bc);
                LDSM4(vbl, sVl + (g * 16 + br) * 40 + bc);
                #pragma unroll
                for (int half = 0; half < 2; half++) {
                    int f = g * 2 + half;
                    MMA_BF16(o[f], ph, vbh[half * 2], vbh[half * 2 + 1]);
                    MMA_BF16(o[f], pl, vbh[half * 2], vbh[half * 2 + 1]);
                    MMA_BF16(o[f], ph, vbl[half * 2], vbl[half * 2 + 1]);
                }
            }
        }
        __syncthreads();
    }

    float inv0 = 1.f / l0, inv1 = 1.f / l1;
    int qi0 = q0 + row0 + (lane >> 2);
    int qi1 = qi0 + 8;
    #pragma unroll
    for (int f = 0; f < 16; f++) {
        int gcol = h * HD_ + f * 8 + 2 * (lane & 3);
        uint32_t hi, lo;
        split2(o[f][0] * inv0, o[f][1] * inv0, hi, lo);
        *(uint32_t*)(oh + (long long)qi0 * D_ + gcol) = hi;
        *(uint32_t*)(ol + (long long)qi0 * D_ + gcol) = lo;
        split2(o[f][2] * inv1, o[f][3] * inv1, hi, lo);
        *(uint32_t*)(oh + (long long)qi1 * D_ + gcol) = hi;
        *(uint32_t*)(ol + (long long)qi1 * D_ + gcol) = lo;
    }
}

// ---------------- fused router: logits + softmax + top-2 ----------------
__global__ void router_topk_kernel(const float* __restrict__ hn,
                                   const float* __restrict__ rw) {
    __shared__ float sx[4][D_];
    __shared__ float slog[4][E_];
    int t0 = blockIdx.x * 4;
    int tid = threadIdx.x;
    for (int c = tid; c < 4 * (D_ / 4); c += 256) {
        int tok = c >> 9;
        int j = c & 511;
        ((float4*)sx[tok])[j] = ((const float4*)(hn + (long long)(t0 + tok) * D_))[j];
    }
    __syncthreads();
    int warp = tid >> 5, lane = tid & 31;
    for (int e8 = 0; e8 < 8; e8++) {
        int e = warp * 8 + e8;
        const float4* w = (const float4*)(rw + (long long)e * D_);
        float a0 = 0.f, a1 = 0.f, a2 = 0.f, a3 = 0.f;
        for (int j = lane; j < D_ / 4; j += 32) {
            float4 wv = w[j];
            float4 x0 = ((const float4*)sx[0])[j];
            float4 x1 = ((const float4*)sx[1])[j];
            float4 x2 = ((const float4*)sx[2])[j];
            float4 x3 = ((const float4*)sx[3])[j];
            a0 += wv.x * x0.x + wv.y * x0.y + wv.z * x0.z + wv.w * x0.w;
            a1 += wv.x * x1.x + wv.y * x1.y + wv.z * x1.z + wv.w * x1.w;
            a2 += wv.x * x2.x + wv.y * x2.y + wv.z * x2.z + wv.w * x2.w;
            a3 += wv.x * x3.x + wv.y * x3.y + wv.z * x3.z + wv.w * x3.w;
        }
        #pragma unroll
        for (int off = 16; off > 0; off >>= 1) {
            a0 += __shfl_xor_sync(0xffffffff, a0, off);
            a1 += __shfl_xor_sync(0xffffffff, a1, off);
            a2 += __shfl_xor_sync(0xffffffff, a2, off);
            a3 += __shfl_xor_sync(0xffffffff, a3, off);
        }
        if (lane == 0) {
            slog[0][e] = a0; slog[1][e] = a1; slog[2][e] = a2; slog[3][e] = a3;
        }
    }
    __syncthreads();
    if (tid < 4) {
        const float* lg = slog[tid];
        int t = t0 + tid;
        float mx = -INFINITY;
        for (int e = 0; e < E_; e++) mx = fmaxf(mx, lg[e]);
        float Z = 0.f;
        float v1 = -INFINITY, v2 = -INFINITY;
        int i1 = 0, i2 = 0;
        for (int e = 0; e < E_; e++) {
            float vv = lg[e];
            Z += __expf(vv - mx);
            if (vv > v1) { v2 = v1; i2 = i1; v1 = vv; i1 = e; }
            else if (vv > v2) { v2 = vv; i2 = e; }
        }
        float invZ = 1.f / Z;
        g_top_e[t * 2 + 0] = i1;
        g_top_e[t * 2 + 1] = i2;
        g_top_s[t * 2 + 0] = __expf(v1 - mx) * invZ;
        g_top_s[t * 2 + 1] = __expf(v2 - mx) * invZ;
    }
}

// ---------------- capacity routing: warp-ballot per expert ----------------
__global__ void route_assign_kernel() {
    int warp = threadIdx.x >> 5;
    int lane = threadIdx.x & 31;
    int e = blockIdx.x * (blockDim.x >> 5) + warp;
    if (e >= E_) return;
    int cnt = 0;
    for (int base = 0; base < T_ * TOPK_; base += 32) {
        int idx = base + lane;
        int te = g_top_e[idx];
        unsigned mask = __ballot_sync(0xffffffff, te == e);
        if (te == e) {
            int pos = cnt + __popc(mask & ((1u << lane) - 1));
            if (pos < CAP_) {
                g_dest[idx] = e * CAP_ + pos;
                g_slot_token[e * CAP_ + pos] = idx >> 1;
                g_slot_scale[e * CAP_ + pos] = g_top_s[idx];
            } else {
                g_dest[idx] = -1;
            }
        }
        cnt += __popc(mask);
    }
    if (lane == 0) g_count[e] = cnt < CAP_ ? cnt : CAP_;
}

// ---------------- gather (scaled) into split expert buffers ----------------
__global__ void gather_kernel(const float* __restrict__ hn) {
    int slot = blockIdx.x;
    int e = slot >> 8;
    int p = slot & 255;
    if (p >= g_count[e]) return;
    __nv_bfloat16* dh = g_bufh + (long long)slot * D_;
    __nv_bfloat16* dl = g_bufl + (long long)slot * D_;
    int t = g_slot_token[slot];
    float sc = g_slot_scale[slot];
    const float* src = hn + (long long)t * D_;
    #pragma unroll
    for (int base = 0; base < D_; base += 1024) {
        int d = base + threadIdx.x * 4;
        float4 vv = *(const float4*)(src + d);
        vv.x *= sc; vv.y *= sc; vv.z *= sc; vv.w *= sc;
        uint32_t h01, l01, h23, l23;
        split2(vv.x, vv.y, h01, l01);
        split2(vv.z, vv.w, h23, l23);
        *(uint2*)(dh + d) = make_uint2(h01, h23);
        *(uint2*)(dl + d) = make_uint2(l01, l23);
    }
}

// ---------------- final: out = h + scattered expert outputs ----------------
__global__ void final_kernel(float* __restrict__ out) {
    int t = blockIdx.x;
    int d0 = g_dest[t * 2 + 0];
    int d1 = g_dest[t * 2 + 1];
    const float* hrow = g_h + (long long)t * D_;
    const float* e0 = (d0 >= 0) ? g_eout + (long long)d0 * D_ : nullptr;
    const float* e1 = (d1 >= 0) ? g_eout + (long long)d1 * D_ : nullptr;
    float* orow = out + (long long)t * D_;
    #pragma unroll
    for (int base = 0; base < D_; base += 1024) {
        int d = base + threadIdx.x * 4;
        float4 vv = *(const float4*)(hrow + d);
        if (e0) {
            float4 a = *(const float4*)(e0 + d);
            vv.x += a.x; vv.y += a.y; vv.z += a.z; vv.w += a.w;
        }
        if (e1) {
            float4 a = *(const float4*)(e1 + d);
            vv.x += a.x; vv.y += a.y; vv.z += a.z; vv.w += a.w;
        }
        *(float4*)(orow + d) = vv;
    }
}

// ---------------- host launcher ----------------
template <typename Tp>
static Tp* sym(const void* s) {
    void* p = nullptr;
    cudaGetSymbolAddress(&p, s);
    return (Tp*)p;
}

extern "C" void kernel_launch(void* const* d_in, const int* in_sizes, int n_in,
                              void* d_out, int out_size) {
    const float* x    = (const float*)d_in[0];
    const float* fcos = (const float*)d_in[1];
    const float* fsin = (const float*)d_in[2];
    const float* anw  = (const float*)d_in[3];
    const float* fnw  = (const float*)d_in[4];
    const float* wq   = (const float*)d_in[5];
    const float* wk   = (const float*)d_in[6];
    const float* wv   = (const float*)d_in[7];
    const float* wo   = (const float*)d_in[8];
    const float* rw   = (const float*)d_in[9];
    const float* w1   = (const float*)d_in[10];
    const float* w2   = (const float*)d_in[11];
    const float* w3   = (const float*)d_in[12];
    float* out = (float*)d_out;

    float* h    = sym<float>(g_h);
    float* hn   = sym<float>(g_hn);
    float* eout = sym<float>(g_eout);

    __nv_bfloat16* xnh = sym<__nv_bfloat16>(g_xnh);
    __nv_bfloat16* xnl = sym<__nv_bfloat16>(g_xnl);
    __nv_bfloat16* qh  = sym<__nv_bfloat16>(g_qh);
    __nv_bfloat16* ql  = sym<__nv_bfloat16>(g_ql);
    __nv_bfloat16* kh  = sym<__nv_bfloat16>(g_kh);
    __nv_bfloat16* kl  = sym<__nv_bfloat16>(g_kl);
    __nv_bfloat16* vth = sym<__nv_bfloat16>(g_vth);
    __nv_bfloat16* vtl = sym<__nv_bfloat16>(g_vtl);
    __nv_bfloat16* ath = sym<__nv_bfloat16>(g_ath);
    __nv_bfloat16* atl = sym<__nv_bfloat16>(g_atl);
    __nv_bfloat16* bufh = sym<__nv_bfloat16>(g_bufh);
    __nv_bfloat16* bufl = sym<__nv_bfloat16>(g_bufl);
    __nv_bfloat16* gateh = sym<__nv_bfloat16>(g_gateh);
    __nv_bfloat16* gatel = sym<__nv_bfloat16>(g_gatel);

    cudaFuncSetAttribute(gemm_os<3, 0, 1, 128>, cudaFuncAttributeMaxDynamicSharedMemorySize, GEMM_SMEM_128);
    cudaFuncSetAttribute(gemm_os<1, 0, 0, 128>, cudaFuncAttributeMaxDynamicSharedMemorySize, GEMM_SMEM_128);
    cudaFuncSetAttribute(gemm_os<2, 1, 2, 64>,  cudaFuncAttributeMaxDynamicSharedMemorySize, GEMM_SMEM_64);
    cudaFuncSetAttribute(gemm_os<0, 1, 0, 64>,  cudaFuncAttributeMaxDynamicSharedMemorySize, GEMM_SMEM_64);
    cudaFuncSetAttribute(attn_mma_kernel, cudaFuncAttributeMaxDynamicSharedMemorySize, ATTN_SMEM);

    // 1. attn rmsnorm -> split planes
    rmsnorm_split_kernel<<<S_, 256>>>(x, anw, xnh, xnl);

    // 2. fused qkv projection (raw fp32 weights, on-the-fly split) + rope epilogue
    gemm_os<3, 0, 1, 128><<<dim3(48, 16, 1), 256, GEMM_SMEM_128>>>(
        xnh, xnl, wq, wk, wv, nullptr, nullptr, S_, 3 * D_, D_, 0, 0, 0, fcos, fsin);

    // 3. V transpose + split
    vtrans_kernel<<<dim3(64, 64), dim3(32, 8)>>>(vth, vtl);

    // 4. flash attention -> split planes (32-key tiles, 3 CTAs/SM)
    attn_mma_kernel<<<dim3(32, 16), 128, ATTN_SMEM>>>(qh, ql, kh, kl, vth, vtl, ath, atl);

    // 5. h = x + attn @ wo^T
    gemm_os<1, 0, 0, 128><<<dim3(16, 16, 1), 256, GEMM_SMEM_128>>>(
        ath, atl, wo, nullptr, nullptr, x, h, S_, D_, D_, 0, 0, 0, nullptr, nullptr);

    // 6. ffn rmsnorm
    rmsnorm_kernel<<<S_, 256>>>(h, fnw, hn);

    // 7. router + capacity assignment
    router_topk_kernel<<<T_ / 4, 256>>>(hn, rw);
    route_assign_kernel<<<2, 1024>>>();

    // 8. gather -> split expert buffers (valid slots only)
    gather_kernel<<<E_ * CAP_, 256>>>(hn);

    // 9. expert FFN: 64-row m-tiles (3-stage pipeline), skip tiles >= count
    gemm_os<2, 1, 2, 64><<<dim3(8, 4, E_), 256, GEMM_SMEM_64>>>(
        bufh, bufl, w1, nullptr, w3, nullptr, nullptr,
        CAP_, 2 * HID_, D_,
        (long long)CAP_ * D_, (long long)HID_ * D_, 0, nullptr, nullptr);
    gemm_os<0, 1, 0, 64><<<dim3(16, 4, E_), 256, GEMM_SMEM_64>>>(
        gateh, gatel, w2, nullptr, nullptr, nullptr, eout,
        CAP_, D_, HID_,
        (long long)CAP_ * HID_, (long long)D_ * HID_, (long long)CAP_ * D_, nullptr, nullptr);

    // 10. out = h + scatter(expert outputs)
    final_kernel<<<T_, 256>>>(out);
}

// round 11
// speedup vs baseline: 1.0820x; 1.0107x over previous
#include <cuda_runtime.h>
#include <cuda_bf16.h>
#include <math.h>
#include <stdint.h>

// ---------------- problem constants ----------------
#define S_  2048
#define D_  2048
#define H_  16
#define HD_ 128
#define E_  64
#define TOPK_ 2
#define HID_ 512
#define CAP_ 256
#define T_  (S_)
#define EPS_ 1e-6f
#define QKSCALE_ 0.08838834764831845f

// ---------------- scratch ----------------
__device__ float g_vf  [S_ * D_];
__device__ float g_h   [S_ * D_];
__device__ float g_hn  [S_ * D_];
__device__ int   g_top_e [T_ * TOPK_];
__device__ float g_top_s [T_ * TOPK_];
__device__ int   g_dest  [T_ * TOPK_];
__device__ int   g_count [E_];
__device__ int   g_slot_token[E_ * CAP_];
__device__ float g_slot_scale[E_ * CAP_];
__device__ float g_eout [E_ * CAP_ * D_];

// bf16 split activation planes
__device__ __nv_bfloat16 g_xnh[S_ * D_],  g_xnl[S_ * D_];
__device__ __nv_bfloat16 g_qh [S_ * D_],  g_ql [S_ * D_];
__device__ __nv_bfloat16 g_kh [S_ * D_],  g_kl [S_ * D_];
__device__ __nv_bfloat16 g_vth[D_ * S_],  g_vtl[D_ * S_];
__device__ __nv_bfloat16 g_ath[S_ * D_],  g_atl[S_ * D_];
__device__ __nv_bfloat16 g_bufh[E_ * CAP_ * D_], g_bufl[E_ * CAP_ * D_];
__device__ __nv_bfloat16 g_gateh[E_ * CAP_ * HID_], g_gatel[E_ * CAP_ * HID_];

// ---------------- helpers ----------------
__device__ __forceinline__ void bsplit(float v, __nv_bfloat16& h, __nv_bfloat16& l) {
    h = __float2bfloat16(v);
    l = __float2bfloat16(v - __bfloat162float(h));
}
__device__ __forceinline__ void split2(float x, float y, uint32_t& hi, uint32_t& lo) {
    __nv_bfloat16 hx = __float2bfloat16(x), hy = __float2bfloat16(y);
    __nv_bfloat16 lx = __float2bfloat16(x - __bfloat162float(hx));
    __nv_bfloat16 ly = __float2bfloat16(y - __bfloat162float(hy));
    __nv_bfloat162 hp = __halves2bfloat162(hx, hy);
    __nv_bfloat162 lp = __halves2bfloat162(lx, ly);
    hi = *(uint32_t*)&hp;
    lo = *(uint32_t*)&lp;
}

#define CP_ASYNC16(dst_sm, src_g) \
    asm volatile("cp.async.cg.shared.global [%0], [%1], 16;\n" :: "r"(dst_sm), "l"(src_g))

#define LDSM4(r, ptr) do { \
    uint32_t _a = (uint32_t)__cvta_generic_to_shared(ptr); \
    asm volatile("ldmatrix.sync.aligned.m8n8.x4.shared.b16 {%0,%1,%2,%3}, [%4];\n" \
                 : "=r"((r)[0]), "=r"((r)[1]), "=r"((r)[2]), "=r"((r)[3]) : "r"(_a)); \
} while (0)

#define MMA_BF16(d, a, b0, b1) \
    asm volatile("mma.sync.aligned.m16n8k16.row.col.f32.bf16.bf16.f32 " \
                 "{%0,%1,%2,%3}, {%4,%5,%6,%7}, {%8,%9}, {%0,%1,%2,%3};\n" \
                 : "+f"((d)[0]), "+f"((d)[1]), "+f"((d)[2]), "+f"((d)[3]) \
                 : "r"((a)[0]), "r"((a)[1]), "r"((a)[2]), "r"((a)[3]), "r"(b0), "r"(b1))

// ---------------- RMSNorm variants ----------------
__global__ void rmsnorm_kernel(const float* __restrict__ x,
                               const float* __restrict__ w,
                               float* __restrict__ out) {
    int s = blockIdx.x;
    const float* row = x + (long long)s * D_;
    float ss = 0.f;
    #pragma unroll
    for (int base = 0; base < D_; base += 1024) {
        float4 v = *(const float4*)(row + base + threadIdx.x * 4);
        ss += v.x * v.x + v.y * v.y + v.z * v.z + v.w * v.w;
    }
    __shared__ float red[256];
    red[threadIdx.x] = ss;
    __syncthreads();
    for (int off = 128; off > 0; off >>= 1) {
        if (threadIdx.x < off) red[threadIdx.x] += red[threadIdx.x + off];
        __syncthreads();
    }
    float scale = rsqrtf(red[0] / (float)D_ + EPS_);
    float* orow = out + (long long)s * D_;
    #pragma unroll
    for (int base = 0; base < D_; base += 1024) {
        int d = base + threadIdx.x * 4;
        float4 v = *(const float4*)(row + d);
        float4 ww = *(const float4*)(w + d);
        v.x *= scale * ww.x; v.y *= scale * ww.y;
        v.z *= scale * ww.z; v.w *= scale * ww.w;
        *(float4*)(orow + d) = v;
    }
}

__global__ void rmsnorm_split_kernel(const float* __restrict__ x,
                                     const float* __restrict__ w,
                                     __nv_bfloat16* __restrict__ oh,
                                     __nv_bfloat16* __restrict__ ol) {
    int s = blockIdx.x;
    const float* row = x + (long long)s * D_;
    float ss = 0.f;
    #pragma unroll
    for (int base = 0; base < D_; base += 1024) {
        float4 v = *(const float4*)(row + base + threadIdx.x * 4);
        ss += v.x * v.x + v.y * v.y + v.z * v.z + v.w * v.w;
    }
    __shared__ float red[256];
    red[threadIdx.x] = ss;
    __syncthreads();
    for (int off = 128; off > 0; off >>= 1) {
        if (threadIdx.x < off) red[threadIdx.x] += red[threadIdx.x + off];
        __syncthreads();
    }
    float scale = rsqrtf(red[0] / (float)D_ + EPS_);
    #pragma unroll
    for (int base = 0; base < D_; base += 1024) {
        int d = base + threadIdx.x * 4;
        float4 v = *(const float4*)(row + d);
        float4 ww = *(const float4*)(w + d);
        v.x *= scale * ww.x; v.y *= scale * ww.y;
        v.z *= scale * ww.z; v.w *= scale * ww.w;
        long long off = (long long)s * D_ + d;
        uint32_t h01, l01, h23, l23;
        split2(v.x, v.y, h01, l01);
        split2(v.z, v.w, h23, l23);
        *(uint2*)(oh + off) = make_uint2(h01, h23);
        *(uint2*)(ol + off) = make_uint2(l01, l23);
    }
}

// ---------------- split-free bf16 tensor-core GEMM (R9/R10 config) ---------
template <int MODE, int SKIP, int BMODE, int MTILE>
__global__ __launch_bounds__(256, 2)
void gemm_os(const __nv_bfloat16* __restrict__ Ah, const __nv_bfloat16* __restrict__ Al,
             const float* __restrict__ B0, const float* __restrict__ B1,
             const float* __restrict__ B2,
             const float* __restrict__ ADD, float* __restrict__ C,
             int M, int N, int K,
             long long sA, long long sB, long long sC,
             const float* __restrict__ fcos, const float* __restrict__ fsin) {
    const int m0 = blockIdx.y * MTILE;
    if (SKIP) {
        if (m0 >= g_count[blockIdx.z]) return;
    }
    constexpr int NST = (MTILE == 64) ? 3 : 2;
    constexpr int AST = MTILE * 40;
    constexpr int MF  = MTILE / 32;
    extern __shared__ char smem_raw[];
    __nv_bfloat16* sAh = (__nv_bfloat16*)smem_raw;
    __nv_bfloat16* sAl = sAh + NST * AST;
    float*         sBf = (float*)(sAl + NST * AST);

    const __nv_bfloat16* Ahp = Ah + (long long)blockIdx.z * sA;
    const __nv_bfloat16* Alp = Al + (long long)blockIdx.z * sA;
    const long long bzsB = (long long)blockIdx.z * sB;
    C += (long long)blockIdx.z * sC;

    const int tid  = threadIdx.x;
    const int lane = tid & 31;
    const int warp = tid >> 5;
    const int wm = warp & 1;
    const int wn = warp >> 1;
    const int n0 = blockIdx.x * 128;

    float acc[MF][4][4];
    #pragma unroll
    for (int i = 0; i < MF; i++)
        #pragma unroll
        for (int j = 0; j < 4; j++)
            #pragma unroll
            for (int r = 0; r < 4; r++) acc[i][j][r] = 0.f;

    auto copyAB = [&](int stage, int k0) {
        __nv_bfloat16* sa = sAh + stage * AST;
        __nv_bfloat16* sl = sAl + stage * AST;
        #pragma unroll
        for (int i = 0; i < MTILE / 64; i++) {
            int ch  = tid + (i << 8);
            int row = ch >> 2;
            int c   = (ch & 3) << 3;
            const __nv_bfloat16* ap = Ahp + (size_t)(m0 + row) * K + k0 + c;
            const __nv_bfloat16* lp = Alp + (size_t)(m0 + row) * K + k0 + c;
            CP_ASYNC16((uint32_t)__cvta_generic_to_shared(sa + row * 40 + c), ap);
            CP_ASYNC16((uint32_t)__cvta_generic_to_shared(sl + row * 40 + c), lp);
        }
        float* sb = sBf + stage * 4608;
        #pragma unroll
        for (int i = 0; i < 4; i++) {
            int ch  = tid + (i << 8);
            int row = ch >> 3;
            int c   = (ch & 7) << 2;
            int n   = n0 + row;
            const float* src;
            if (BMODE == 0) {
                src = B0 + bzsB + (size_t)n * K;
            } else if (BMODE == 1) {
                int sel = n >> 11;
                const float* w = (sel == 0) ? B0 : ((sel == 1) ? B1 : B2);
                src = w + (size_t)(n & 2047) * K;
            } else {
                const float* w = (n & 1) ? B2 : B0;
                src = w + bzsB + (size_t)(n >> 1) * K;
            }
            CP_ASYNC16((uint32_t)__cvta_generic_to_shared(sb + row * 36 + c), src + k0 + c);
        }
        asm volatile("cp.async.commit_group;\n");
    };

    auto compute = [&](int st) {
        const __nv_bfloat16* sa = sAh + st * AST;
        const __nv_bfloat16* sl = sAl + st * AST;
        const float* sb = sBf + st * 4608;
        #pragma unroll
        for (int ks = 0; ks < 32; ks += 16) {
            uint32_t bh[4][2], bl[4][2];
            const int bn = wn * 32 + (lane >> 2);
            const int bk = ks + ((lane & 3) << 1);
            #pragma unroll
            for (int g = 0; g < 4; g++) {
                const float* p = sb + (bn + g * 8) * 36 + bk;
                float2 x0 = *(const float2*)p;
                float2 x1 = *(const float2*)(p + 8);
                split2(x0.x, x0.y, bh[g][0], bl[g][0]);
                split2(x1.x, x1.y, bh[g][1], bl[g][1]);
            }
            const int ar = lane & 15;
            const int ac = ks + ((lane >> 4) << 3);
            #pragma unroll
            for (int mf = 0; mf < MF; mf++) {
                uint32_t a4[4];
                LDSM4(a4, sa + (wm * (MTILE / 2) + mf * 16 + ar) * 40 + ac);
                #pragma unroll
                for (int nf = 0; nf < 4; nf++)
                    MMA_BF16(acc[mf][nf], a4, bh[nf][0], bh[nf][1]);
                #pragma unroll
                for (int nf = 0; nf < 4; nf++)
                    MMA_BF16(acc[mf][nf], a4, bl[nf][0], bl[nf][1]);
                LDSM4(a4, sl + (wm * (MTILE / 2) + mf * 16 + ar) * 40 + ac);
                #pragma unroll
                for (int nf = 0; nf < 4; nf++)
                    MMA_BF16(acc[mf][nf], a4, bh[nf][0], bh[nf][1]);
            }
        }
    };

    const int KT = K >> 5;
    copyAB(0, 0);
    if (KT > 1) copyAB(1, 32);

    if (NST == 3) {
        for (int t = 0; t < KT; t++) {
            if (t == KT - 1) {
                asm volatile("cp.async.wait_group 0;\n");
            } else {
                asm volatile("cp.async.wait_group 1;\n");
            }
            __syncthreads();
            if (t + 2 < KT) copyAB((t + 2) % 3, (t + 2) << 5);
            compute(t % 3);
        }
    } else {
        for (int t = 0; t < KT; t++) {
            const int st = t & 1;
            if (t == KT - 1) {
                asm volatile("cp.async.wait_group 0;\n");
            } else {
                asm volatile("cp.async.wait_group 1;\n");
            }
            __syncthreads();
            compute(st);
            __syncthreads();
            if (t + 2 < KT) copyAB(st, (t + 2) << 5);
        }
    }

    const int gq = lane >> 2, th = lane & 3;
    #pragma unroll
    for (int mf = 0; mf < MF; mf++) {
        #pragma unroll
        for (int nf = 0; nf < 4; nf++) {
            int row = m0 + wm * (MTILE / 2) + mf * 16 + gq;
            int col = n0 + wn * 32 + nf * 8 + th * 2;
            float2 v0 = make_float2(acc[mf][nf][0], acc[mf][nf][1]);
            float2 v1 = make_float2(acc[mf][nf][2], acc[mf][nf][3]);
            if (MODE == 0 || MODE == 1) {
                if (MODE == 1) {
                    float2 x0 = *(const float2*)(ADD + (size_t)row * N + col);
                    float2 x1 = *(const float2*)(ADD + (size_t)(row + 8) * N + col);
                    v0.x += x0.x; v0.y += x0.y;
                    v1.x += x1.x; v1.y += x1.y;
                }
                *(float2*)(C + (size_t)row * N + col) = v0;
                *(float2*)(C + (size_t)(row + 8) * N + col) = v1;
            } else if (MODE == 2) {
                int j = col >> 1;
                long long slot0 = (long long)blockIdx.z * CAP_ + row;
                float r0 = v0.x * (1.f / (1.f + __expf(-v0.x))) * v0.y;
                float r1 = v1.x * (1.f / (1.f + __expf(-v1.x))) * v1.y;
                __nv_bfloat16 hb, lb;
                bsplit(r0, hb, lb);
                g_gateh[slot0 * HID_ + j] = hb;
                g_gatel[slot0 * HID_ + j] = lb;
                bsplit(r1, hb, lb);
                g_gateh[(slot0 + 8) * HID_ + j] = hb;
                g_gatel[(slot0 + 8) * HID_ + j] = lb;
            } else {  // MODE 3
                if (col < 2 * D_) {
                    int lc = col & (D_ - 1);
                    int i  = (lc & 127) >> 1;
                    bool isq = col < D_;
                    float sc = isq ? QKSCALE_ : 1.f;
                    __nv_bfloat16* dh = isq ? g_qh : g_kh;
                    __nv_bfloat16* dl = isq ? g_ql : g_kl;
                    float c0 = fcos[row * 64 + i], s0 = fsin[row * 64 + i];
                    float y0 = (v0.x * c0 - v0.y * s0) * sc;
                    float y1 = (v0.x * s0 + v0.y * c0) * sc;
                    uint32_t hi, lo;
                    split2(y0, y1, hi, lo);
                    *(uint32_t*)(dh + (long long)row * D_ + lc) = hi;
                    *(uint32_t*)(dl + (long long)row * D_ + lc) = lo;
                    float c1 = fcos[(row + 8) * 64 + i], s1 = fsin[(row + 8) * 64 + i];
                    y0 = (v1.x * c1 - v1.y * s1) * sc;
                    y1 = (v1.x * s1 + v1.y * c1) * sc;
                    split2(y0, y1, hi, lo);
                    *(uint32_t*)(dh + (long long)(row + 8) * D_ + lc) = hi;
                    *(uint32_t*)(dl + (long long)(row + 8) * D_ + lc) = lo;
                } else {
                    int lc = col - 2 * D_;
                    *(float2*)(g_vf + (long long)row * D_ + lc) = v0;
                    *(float2*)(g_vf + (long long)(row + 8) * D_ + lc) = v1;
                }
            }
        }
    }
}

#define GEMM_SMEM_128 (2 * 2 * (128 * 40) * 2 + 2 * 4608 * 4)   // 77824 B (2-stage)
#define GEMM_SMEM_64  (3 * 2 * (64 * 40) * 2 + 3 * 4608 * 4)    // 86016 B (3-stage)

// ---------------- V transpose + split ----------------
__global__ void vtrans_kernel(__nv_bfloat16* __restrict__ vth,
                              __nv_bfloat16* __restrict__ vtl) {
    __shared__ float tile[32][33];
    int s0 = blockIdx.x * 32;
    int d0 = blockIdx.y * 32;
    int tx = threadIdx.x, ty = threadIdx.y;
    #pragma unroll
    for (int i = 0; i < 4; i++) {
        int r = ty + i * 8;
        tile[r][tx] = g_vf[(long long)(s0 + r) * D_ + d0 + tx];
    }
    __syncthreads();
    #pragma unroll
    for (int i = 0; i < 4; i++) {
        int dr = ty + i * 8;
        float v = tile[tx][dr];
        __nv_bfloat16 hv, lv;
        bsplit(v, hv, lv);
        long long off = (long long)(d0 + dr) * S_ + s0 + tx;
        vth[off] = hv;
        vtl[off] = lv;
    }
}

// ---------------- flash attention, no-max softmax, 32-key tiles ------------
// Scores are bounded (~|s|<10 for rms-normed inputs); exp never overflows fp32.
// l accumulated per-thread across tiles; single quad-reduce in epilogue.
#define ATTN_SMEM ((2 * 64 * 136 + 2 * 32 * 136 + 2 * 128 * 40) * 2)   // 72704 B
__global__ __launch_bounds__(128, 3)
void attn_mma_kernel(const __nv_bfloat16* __restrict__ qh, const __nv_bfloat16* __restrict__ ql,
                     const __nv_bfloat16* __restrict__ kh, const __nv_bfloat16* __restrict__ kl,
                     const __nv_bfloat16* __restrict__ vth, const __nv_bfloat16* __restrict__ vtl,
                     __nv_bfloat16* __restrict__ oh, __nv_bfloat16* __restrict__ ol) {
    extern __shared__ __nv_bfloat16 dsm[];
    __nv_bfloat16* sQh = dsm;                   // [64][136]
    __nv_bfloat16* sQl = sQh + 64 * 136;
    __nv_bfloat16* sKh = sQl + 64 * 136;        // [32][136]
    __nv_bfloat16* sKl = sKh + 32 * 136;
    __nv_bfloat16* sVh = sKl + 32 * 136;        // [128][40]
    __nv_bfloat16* sVl = sVh + 128 * 40;

    const int tid  = threadIdx.x;
    const int lane = tid & 31;
    const int warp = tid >> 5;
    const int h  = blockIdx.y;
    const int qb = gridDim.x - 1 - blockIdx.x;
    const int q0 = qb * 64;
    const int row0 = warp * 16;

    // Q tile (persists) — group 0
    for (int c = tid; c < 1024; c += 128) {
        int r = c >> 4, j = (c & 15) << 3;
        long long g = (long long)(q0 + r) * D_ + h * HD_ + j;
        CP_ASYNC16((uint32_t)__cvta_generic_to_shared(sQh + r * 136 + j), qh + g);
        CP_ASYNC16((uint32_t)__cvta_generic_to_shared(sQl + r * 136 + j), ql + g);
    }
    asm volatile("cp.async.commit_group;\n");

    float l0 = 0.f, l1 = 0.f;
    float o[16][4];
    #pragma unroll
    for (int f = 0; f < 16; f++)
        #pragma unroll
        for (int r = 0; r < 4; r++) o[f][r] = 0.f;

    const int ntiles = 2 * qb + 2;
    for (int kt = 0; kt < ntiles; kt++) {
        const int k0 = kt * 32;
        for (int c = tid; c < 512; c += 128) {
            int r = c >> 4, j = (c & 15) << 3;
            long long g = (long long)(k0 + r) * D_ + h * HD_ + j;
            CP_ASYNC16((uint32_t)__cvta_generic_to_shared(sKh + r * 136 + j), kh + g);
            CP_ASYNC16((uint32_t)__cvta_generic_to_shared(sKl + r * 136 + j), kl + g);
        }
        asm volatile("cp.async.commit_group;\n");
        for (int c = tid; c < 512; c += 128) {
            int r = c >> 2, j = (c & 3) << 3;
            long long g = (long long)(h * HD_ + r) * S_ + k0 + j;
            CP_ASYNC16((uint32_t)__cvta_generic_to_shared(sVh + r * 40 + j), vth + g);
            CP_ASYNC16((uint32_t)__cvta_generic_to_shared(sVl + r * 40 + j), vtl + g);
        }
        asm volatile("cp.async.commit_group;\n");
        asm volatile("cp.async.wait_group 1;\n");
        __syncthreads();

        float sc[4][4];
        #pragma unroll
        for (int f = 0; f < 4; f++)
            #pragma unroll
            for (int r = 0; r < 4; r++) sc[f][r] = 0.f;

        #pragma unroll
        for (int ks = 0; ks < 8; ks++) {
            uint32_t ah[4], al[4];
            int ar = lane & 15;
            int ac = ks * 16 + ((lane >> 4) << 3);
            LDSM4(ah, sQh + (row0 + ar) * 136 + ac);
            LDSM4(al, sQl + (row0 + ar) * 136 + ac);
            int br = (lane & 7) + ((lane >> 4) << 3);
            int bc = ks * 16 + (((lane >> 3) & 1) << 3);
            #pragma unroll
            for (int g = 0; g < 2; g++) {
                uint32_t bh[4], bl[4];
                LDSM4(bh, sKh + (g * 16 + br) * 136 + bc);
                LDSM4(bl, sKl + (g * 16 + br) * 136 + bc);
                #pragma unroll
                for (int half = 0; half < 2; half++) {
                    int f = g * 2 + half;
                    MMA_BF16(sc[f], ah, bh[half * 2], bh[half * 2 + 1]);
                    MMA_BF16(sc[f], al, bh[half * 2], bh[half * 2 + 1]);
                    MMA_BF16(sc[f], ah, bl[half * 2], bl[half * 2 + 1]);
                }
            }
        }

        asm volatile("cp.async.wait_group 0;\n");
        __syncthreads();

        int qi0 = q0 + row0 + (lane >> 2);
        if (k0 + 31 > q0 + row0) {      // diagonal region for this warp
            #pragma unroll
            for (int f = 0; f < 4; f++) {
                int ki = k0 + f * 8 + 2 * (lane & 3);
                if (ki > qi0)         sc[f][0] = -INFINITY;
                if (ki + 1 > qi0)     sc[f][1] = -INFINITY;
                if (ki > qi0 + 8)     sc[f][2] = -INFINITY;
                if (ki + 1 > qi0 + 8) sc[f][3] = -INFINITY;
            }
        }

        // unnormalized softmax: exp directly, per-thread l accumulation
        #pragma unroll
        for (int f = 0; f < 4; f++) {
            sc[f][0] = __expf(sc[f][0]);
            sc[f][1] = __expf(sc[f][1]);
            sc[f][2] = __expf(sc[f][2]);
            sc[f][3] = __expf(sc[f][3]);
            l0 += sc[f][0] + sc[f][1];
            l1 += sc[f][2] + sc[f][3];
        }

        // P·V over 32-key chunk (no rescale needed)
        #pragma unroll
        for (int ks = 0; ks < 2; ks++) {
            uint32_t ph[4], pl[4];
            split2(sc[2 * ks][0],     sc[2 * ks][1],     ph[0], pl[0]);
            split2(sc[2 * ks][2],     sc[2 * ks][3],     ph[1], pl[1]);
            split2(sc[2 * ks + 1][0], sc[2 * ks + 1][1], ph[2], pl[2]);
            split2(sc[2 * ks + 1][2], sc[2 * ks + 1][3], ph[3], pl[3]);
            int br = (lane & 7) + ((lane >> 4) << 3);
            int bc = ks * 16 + (((lane >> 3) & 1) << 3);
            #pragma unroll
            for (int g = 0; g < 8; g++) {
                uint32_t vbh[4], vbl[4];
                LDSM4(vbh, sVh + (g * 16 + br) * 40 + bc);
                LDSM4(vbl, sVl + (g * 16 + br) * 40 + bc);
                #pragma unroll
                for (int half = 0; half < 2; half++) {
                    int f = g * 2 + half;
                    MMA_BF16(o[f], ph, vbh[half * 2], vbh[half * 2 + 1]);
                    MMA_BF16(o[f], pl, vbh[half * 2], vbh[half * 2 + 1]);
                    MMA_BF16(o[f], ph, vbl[half * 2], vbl[half * 2 + 1]);
                }
            }
        }
        __syncthreads();
    }

    // single quad reduce of l, then normalize + store
    l0 += __shfl_xor_sync(0xffffffff, l0, 1);
    l0 += __shfl_xor_sync(0xffffffff, l0, 2);
    l1 += __shfl_xor_sync(0xffffffff, l1, 1);
    l1 += __shfl_xor_sync(0xffffffff, l1, 2);
    float inv0 = 1.f / l0, inv1 = 1.f / l1;
    int qi0 = q0 + row0 + (lane >> 2);
    int qi1 = qi0 + 8;
    #pragma unroll
    for (int f = 0; f < 16; f++) {
        int gcol = h * HD_ + f * 8 + 2 * (lane & 3);
        uint32_t hi, lo;
        split2(o[f][0] * inv0, o[f][1] * inv0, hi, lo);
        *(uint32_t*)(oh + (long long)qi0 * D_ + gcol) = hi;
        *(uint32_t*)(ol + (long long)qi0 * D_ + gcol) = lo;
        split2(o[f][2] * inv1, o[f][3] * inv1, hi, lo);
        *(uint32_t*)(oh + (long long)qi1 * D_ + gcol) = hi;
        *(uint32_t*)(ol + (long long)qi1 * D_ + gcol) = lo;
    }
}

// ---------------- fused router: logits + softmax + top-2 ----------------
__global__ void router_topk_kernel(const float* __restrict__ hn,
                                   const float* __restrict__ rw) {
    __shared__ float sx[4][D_];
    __shared__ float slog[4][E_];
    int t0 = blockIdx.x * 4;
    int tid = threadIdx.x;
    for (int c = tid; c < 4 * (D_ / 4); c += 256) {
        int tok = c >> 9;
        int j = c & 511;
        ((float4*)sx[tok])[j] = ((const float4*)(hn + (long long)(t0 + tok) * D_))[j];
    }
    __syncthreads();
    int warp = tid >> 5, lane = tid & 31;
    for (int e8 = 0; e8 < 8; e8++) {
        int e = warp * 8 + e8;
        const float4* w = (const float4*)(rw + (long long)e * D_);
        float a0 = 0.f, a1 = 0.f, a2 = 0.f, a3 = 0.f;
        for (int j = lane; j < D_ / 4; j += 32) {
            float4 wv = w[j];
            float4 x0 = ((const float4*)sx[0])[j];
            float4 x1 = ((const float4*)sx[1])[j];
            float4 x2 = ((const float4*)sx[2])[j];
            float4 x3 = ((const float4*)sx[3])[j];
            a0 += wv.x * x0.x + wv.y * x0.y + wv.z * x0.z + wv.w * x0.w;
            a1 += wv.x * x1.x + wv.y * x1.y + wv.z * x1.z + wv.w * x1.w;
            a2 += wv.x * x2.x + wv.y * x2.y + wv.z * x2.z + wv.w * x2.w;
            a3 += wv.x * x3.x + wv.y * x3.y + wv.z * x3.z + wv.w * x3.w;
        }
        #pragma unroll
        for (int off = 16; off > 0; off >>= 1) {
            a0 += __shfl_xor_sync(0xffffffff, a0, off);
            a1 += __shfl_xor_sync(0xffffffff, a1, off);
            a2 += __shfl_xor_sync(0xffffffff, a2, off);
            a3 += __shfl_xor_sync(0xffffffff, a3, off);
        }
        if (lane == 0) {
            slog[0][e] = a0; slog[1][e] = a1; slog[2][e] = a2; slog[3][e] = a3;
        }
    }
    __syncthreads();
    if (tid < 4) {
        const float* lg = slog[tid];
        int t = t0 + tid;
        float mx = -INFINITY;
        for (int e = 0; e < E_; e++) mx = fmaxf(mx, lg[e]);
        float Z = 0.f;
        float v1 = -INFINITY, v2 = -INFINITY;
        int i1 = 0, i2 = 0;
        for (int e = 0; e < E_; e++) {
            float vv = lg[e];
            Z += __expf(vv - mx);
            if (vv > v1) { v2 = v1; i2 = i1; v1 = vv; i1 = e; }
            else if (vv > v2) { v2 = vv; i2 = e; }
        }
        float invZ = 1.f / Z;
        g_top_e[t * 2 + 0] = i1;
        g_top_e[t * 2 + 1] = i2;
        g_top_s[t * 2 + 0] = __expf(v1 - mx) * invZ;
        g_top_s[t * 2 + 1] = __expf(v2 - mx) * invZ;
    }
}

// ---------------- capacity routing: warp-ballot per expert ----------------
__global__ void route_assign_kernel() {
    int warp = threadIdx.x >> 5;
    int lane = threadIdx.x & 31;
    int e = blockIdx.x * (blockDim.x >> 5) + warp;
    if (e >= E_) return;
    int cnt = 0;
    for (int base = 0; base < T_ * TOPK_; base += 32) {
        int idx = base + lane;
        int te = g_top_e[idx];
        unsigned mask = __ballot_sync(0xffffffff, te == e);
        if (te == e) {
            int pos = cnt + __popc(mask & ((1u << lane) - 1));
            if (pos < CAP_) {
                g_dest[idx] = e * CAP_ + pos;
                g_slot_token[e * CAP_ + pos] = idx >> 1;
                g_slot_scale[e * CAP_ + pos] = g_top_s[idx];
            } else {
                g_dest[idx] = -1;
            }
        }
        cnt += __popc(mask);
    }
    if (lane == 0) g_count[e] = cnt < CAP_ ? cnt : CAP_;
}

// ---------------- gather (scaled) into split expert buffers ----------------
__global__ void gather_kernel(const float* __restrict__ hn) {
    int slot = blockIdx.x;
    int e = slot >> 8;
    int p = slot & 255;
    if (p >= g_count[e]) return;
    __nv_bfloat16* dh = g_bufh + (long long)slot * D_;
    __nv_bfloat16* dl = g_bufl + (long long)slot * D_;
    int t = g_slot_token[slot];
    float sc = g_slot_scale[slot];
    const float* src = hn + (long long)t * D_;
    #pragma unroll
    for (int base = 0; base < D_; base += 1024) {
        int d = base + threadIdx.x * 4;
        float4 vv = *(const float4*)(src + d);
        vv.x *= sc; vv.y *= sc; vv.z *= sc; vv.w *= sc;
        uint32_t h01, l01, h23, l23;
        split2(vv.x, vv.y, h01, l01);
        split2(vv.z, vv.w, h23, l23);
        *(uint2*)(dh + d) = make_uint2(h01, h23);
        *(uint2*)(dl + d) = make_uint2(l01, l23);
    }
}

// ---------------- final: out = h + scattered expert outputs ----------------
__global__ void final_kernel(float* __restrict__ out) {
    int t = blockIdx.x;
    int d0 = g_dest[t * 2 + 0];
    int d1 = g_dest[t * 2 + 1];
    const float* hrow = g_h + (long long)t * D_;
    const float* e0 = (d0 >= 0) ? g_eout + (long long)d0 * D_ : nullptr;
    const float* e1 = (d1 >= 0) ? g_eout + (long long)d1 * D_ : nullptr;
    float* orow = out + (long long)t * D_;
    #pragma unroll
    for (int base = 0; base < D_; base += 1024) {
        int d = base + threadIdx.x * 4;
        float4 vv = *(const float4*)(hrow + d);
        if (e0) {
            float4 a = *(const float4*)(e0 + d);
            vv.x += a.x; vv.y += a.y; vv.z += a.z; vv.w += a.w;
        }
        if (e1) {
            float4 a = *(const float4*)(e1 + d);
            vv.x += a.x; vv.y += a.y; vv.z += a.z; vv.w += a.w;
        }
        *(float4*)(orow + d) = vv;
    }
}

// ---------------- host launcher ----------------
template <typename Tp>
static Tp* sym(const void* s) {
    void* p = nullptr;
    cudaGetSymbolAddress(&p, s);
    return (Tp*)p;
}

extern "C" void kernel_launch(void* const* d_in, const int* in_sizes, int n_in,
                              void* d_out, int out_size) {
    const float* x    = (const float*)d_in[0];
    const float* fcos = (const float*)d_in[1];
    const float* fsin = (const float*)d_in[2];
    const float* anw  = (const float*)d_in[3];
    const float* fnw  = (const float*)d_in[4];
    const float* wq   = (const float*)d_in[5];
    const float* wk   = (const float*)d_in[6];
    const float* wv   = (const float*)d_in[7];
    const float* wo   = (const float*)d_in[8];
    const float* rw   = (const float*)d_in[9];
    const float* w1   = (const float*)d_in[10];
    const float* w2   = (const float*)d_in[11];
    const float* w3   = (const float*)d_in[12];
    float* out = (float*)d_out;

    float* h    = sym<float>(g_h);
    float* hn   = sym<float>(g_hn);
    float* eout = sym<float>(g_eout);

    __nv_bfloat16* xnh = sym<__nv_bfloat16>(g_xnh);
    __nv_bfloat16* xnl = sym<__nv_bfloat16>(g_xnl);
    __nv_bfloat16* qh  = sym<__nv_bfloat16>(g_qh);
    __nv_bfloat16* ql  = sym<__nv_bfloat16>(g_ql);
    __nv_bfloat16* kh  = sym<__nv_bfloat16>(g_kh);
    __nv_bfloat16* kl  = sym<__nv_bfloat16>(g_kl);
    __nv_bfloat16* vth = sym<__nv_bfloat16>(g_vth);
    __nv_bfloat16* vtl = sym<__nv_bfloat16>(g_vtl);
    __nv_bfloat16* ath = sym<__nv_bfloat16>(g_ath);
    __nv_bfloat16* atl = sym<__nv_bfloat16>(g_atl);
    __nv_bfloat16* bufh = sym<__nv_bfloat16>(g_bufh);
    __nv_bfloat16* bufl = sym<__nv_bfloat16>(g_bufl);
    __nv_bfloat16* gateh = sym<__nv_bfloat16>(g_gateh);
    __nv_bfloat16* gatel = sym<__nv_bfloat16>(g_gatel);

    cudaFuncSetAttribute(gemm_os<3, 0, 1, 128>, cudaFuncAttributeMaxDynamicSharedMemorySize, GEMM_SMEM_128);
    cudaFuncSetAttribute(gemm_os<1, 0, 0, 128>, cudaFuncAttributeMaxDynamicSharedMemorySize, GEMM_SMEM_128);
    cudaFuncSetAttribute(gemm_os<2, 1, 2, 64>,  cudaFuncAttributeMaxDynamicSharedMemorySize, GEMM_SMEM_64);
    cudaFuncSetAttribute(gemm_os<0, 1, 0, 64>,  cudaFuncAttributeMaxDynamicSharedMemorySize, GEMM_SMEM_64);
    cudaFuncSetAttribute(attn_mma_kernel, cudaFuncAttributeMaxDynamicSharedMemorySize, ATTN_SMEM);

    // 1. attn rmsnorm -> split planes
    rmsnorm_split_kernel<<<S_, 256>>>(x, anw, xnh, xnl);

    // 2. fused qkv projection (raw fp32 weights, on-the-fly split) + rope epilogue
    gemm_os<3, 0, 1, 128><<<dim3(48, 16, 1), 256, GEMM_SMEM_128>>>(
        xnh, xnl, wq, wk, wv, nullptr, nullptr, S_, 3 * D_, D_, 0, 0, 0, fcos, fsin);

    // 3. V transpose + split
    vtrans_kernel<<<dim3(64, 64), dim3(32, 8)>>>(vth, vtl);

    // 4. flash attention -> split planes (no-max softmax, 32-key tiles)
    attn_mma_kernel<<<dim3(32, 16), 128, ATTN_SMEM>>>(qh, ql, kh, kl, vth, vtl, ath, atl);

    // 5. h = x + attn @ wo^T
    gemm_os<1, 0, 0, 128><<<dim3(16, 16, 1), 256, GEMM_SMEM_128>>>(
        ath, atl, wo, nullptr, nullptr, x, h, S_, D_, D_, 0, 0, 0, nullptr, nullptr);

    // 6. ffn rmsnorm
    rmsnorm_kernel<<<S_, 256>>>(h, fnw, hn);

    // 7. router + capacity assignment
    router_topk_kernel<<<T_ / 4, 256>>>(hn, rw);
    route_assign_kernel<<<2, 1024>>>();

    // 8. gather -> split expert buffers (valid slots only)
    gather_kernel<<<E_ * CAP_, 256>>>(hn);

    // 9. expert FFN: 64-row m-tiles (3-stage pipeline), skip tiles >= count
    gemm_os<2, 1, 2, 64><<<dim3(8, 4, E_), 256, GEMM_SMEM_64>>>(
        bufh, bufl, w1, nullptr, w3, nullptr, nullptr,
        CAP_, 2 * HID_, D_,
        (long long)CAP_ * D_, (long long)HID_ * D_, 0, nullptr, nullptr);
    gemm_os<0, 1, 0, 64><<<dim3(16, 4, E_), 256, GEMM_SMEM_64>>>(
        gateh, gatel, w2, nullptr, nullptr, nullptr, eout,
        CAP_, D_, HID_,
        (long long)CAP_ * HID_, (long long)D_ * HID_, (long long)CAP_ * D_, nullptr, nullptr);

    // 10. out = h + scatter(expert outputs)
    final_kernel<<<T_, 256>>>(out);
}